// round 1
// baseline (speedup 1.0000x reference)
#include <cuda_runtime.h>
#include <math.h>

// Problem constants
#define BB 2
#define SS 2048
#define HH 1024
#define NH 16
#define HD 64
#define RR 64
#define MM (BB*SS)   // 4096 tokens
#define SCALE 0.125f // 1/sqrt(64)

// ---------------- scratch (device globals: allocation-free) ----------------
__device__ float g_WqF[HH*HH];
__device__ float g_WkF[HH*HH];
__device__ float g_bqF[HH];
__device__ float g_bkF[HH];
__device__ float g_QL[MM*HH];
__device__ float g_KL[MM*HH];
__device__ float g_V [MM*HH];
__device__ float g_CTX[MM*HH];

// ---------------- weight fold: Wf[:, h*64+r] = sum_d W[:, h*64+d]*Wl[d][r] --
__global__ __launch_bounds__(256) void fold_w_kernel(
    const float* __restrict__ W, const float* __restrict__ Wl,
    float* __restrict__ Wf) {
  __shared__ float Ws[64][65];   // [row within tile][d]
  __shared__ float Ls[64][65];   // [d][r]
  const int h  = blockIdx.x;
  const int i0 = blockIdx.y * 64;
  const int t  = threadIdx.x;
  for (int idx = t; idx < 64*64; idx += 256) {
    int rr = idx >> 6, cc = idx & 63;
    Ws[rr][cc] = W[(i0 + rr) * HH + h * 64 + cc];
    Ls[rr][cc] = Wl[rr * 64 + cc];
  }
  __syncthreads();
  const int ty = t >> 4, tx = t & 15;
  float acc[4][4];
#pragma unroll
  for (int i = 0; i < 4; i++)
#pragma unroll
    for (int j = 0; j < 4; j++) acc[i][j] = 0.f;
#pragma unroll 8
  for (int k = 0; k < 64; k++) {
    float a[4], b[4];
#pragma unroll
    for (int i = 0; i < 4; i++) a[i] = Ws[ty*4+i][k];
#pragma unroll
    for (int j = 0; j < 4; j++) b[j] = Ls[k][tx*4+j];
#pragma unroll
    for (int i = 0; i < 4; i++)
#pragma unroll
      for (int j = 0; j < 4; j++) acc[i][j] += a[i] * b[j];
  }
#pragma unroll
  for (int i = 0; i < 4; i++)
#pragma unroll
    for (int j = 0; j < 4; j++)
      Wf[(i0 + ty*4 + i) * HH + h * 64 + tx*4 + j] = acc[i][j];
}

// bf[h*64+r] = bl[r] + sum_d b[h*64+d]*Wl[d][r]
__global__ void fold_b_kernel(const float* __restrict__ b,
                              const float* __restrict__ Wl,
                              const float* __restrict__ bl,
                              float* __restrict__ bf) {
  int idx = blockIdx.x * 256 + threadIdx.x;
  if (idx < HH) {
    int h = idx >> 6, r = idx & 63;
    float acc = bl[r];
    for (int d = 0; d < 64; d++) acc += b[h * 64 + d] * Wl[d * 64 + r];
    bf[idx] = acc;
  }
}

// ---------------- GEMM + bias: C[4096,1024] = A @ W + bias ------------------
// BM=128 BN=128 BK=16, 256 threads, 8x8 microtile, conflict-free float4 frags
__global__ __launch_bounds__(256) void gemm_bias_kernel(
    const float* __restrict__ A, const float* __restrict__ W,
    const float* __restrict__ bias, float* __restrict__ C) {
  __shared__ float As[16][132];  // [k][m] (transposed)
  __shared__ float Bs[16][132];  // [k][n]
  const int m0 = blockIdx.y * 128, n0 = blockIdx.x * 128;
  const int t = threadIdx.x, ty = t >> 4, tx = t & 15;
  const int arow = t >> 2;            // 0..63
  const int akq  = (t & 3) << 2;      // 0,4,8,12
  const int brow = t >> 5;            // 0..7
  const int bcol = (t & 31) << 2;     // 0..124

  float acc[8][8];
#pragma unroll
  for (int i = 0; i < 8; i++)
#pragma unroll
    for (int j = 0; j < 8; j++) acc[i][j] = 0.f;

  for (int k0 = 0; k0 < HH; k0 += 16) {
    float4 a0 = *(const float4*)&A[(m0 + arow)      * HH + k0 + akq];
    float4 a1 = *(const float4*)&A[(m0 + arow + 64) * HH + k0 + akq];
    float4 b0 = *(const float4*)&W[(k0 + brow)     * HH + n0 + bcol];
    float4 b1 = *(const float4*)&W[(k0 + brow + 8) * HH + n0 + bcol];
    __syncthreads();  // previous compute done before overwrite
    As[akq+0][arow] = a0.x; As[akq+1][arow] = a0.y;
    As[akq+2][arow] = a0.z; As[akq+3][arow] = a0.w;
    As[akq+0][arow+64] = a1.x; As[akq+1][arow+64] = a1.y;
    As[akq+2][arow+64] = a1.z; As[akq+3][arow+64] = a1.w;
    *(float4*)&Bs[brow][bcol]     = b0;
    *(float4*)&Bs[brow + 8][bcol] = b1;
    __syncthreads();
#pragma unroll
    for (int kk = 0; kk < 16; kk++) {
      float4 af0 = *(const float4*)&As[kk][ty*4];
      float4 af1 = *(const float4*)&As[kk][64 + ty*4];
      float4 bf0 = *(const float4*)&Bs[kk][tx*4];
      float4 bf1 = *(const float4*)&Bs[kk][64 + tx*4];
      float a[8] = {af0.x, af0.y, af0.z, af0.w, af1.x, af1.y, af1.z, af1.w};
      float b[8] = {bf0.x, bf0.y, bf0.z, bf0.w, bf1.x, bf1.y, bf1.z, bf1.w};
#pragma unroll
      for (int i = 0; i < 8; i++)
#pragma unroll
        for (int j = 0; j < 8; j++) acc[i][j] += a[i] * b[j];
    }
  }
  float4 bi0 = *(const float4*)&bias[n0 + tx*4];
  float4 bi1 = *(const float4*)&bias[n0 + 64 + tx*4];
  float bi[8] = {bi0.x, bi0.y, bi0.z, bi0.w, bi1.x, bi1.y, bi1.z, bi1.w};
#pragma unroll
  for (int i = 0; i < 8; i++) {
    int row = m0 + ((i < 4) ? (ty*4 + i) : (64 + ty*4 + i - 4));
    float4 o0 = make_float4(acc[i][0]+bi[0], acc[i][1]+bi[1],
                            acc[i][2]+bi[2], acc[i][3]+bi[3]);
    float4 o1 = make_float4(acc[i][4]+bi[4], acc[i][5]+bi[5],
                            acc[i][6]+bi[6], acc[i][7]+bi[7]);
    *(float4*)&C[row * HH + n0 + tx*4]      = o0;
    *(float4*)&C[row * HH + n0 + 64 + tx*4] = o1;
  }
}

// ---------------- fused flash attention (fp32, 64q x 64k tiles) -------------
#define PAD 68
#define ATTN_SMEM (4 * 64 * PAD * 4)

__global__ __launch_bounds__(256, 2) void attn_kernel(
    const float* __restrict__ QL, const float* __restrict__ KL,
    const float* __restrict__ V,  const float* __restrict__ mask,
    float* __restrict__ CTX) {
  extern __shared__ float sm[];
  float (*Qs)[PAD] = (float(*)[PAD])(sm);                 // [r][q]
  float (*Ks)[PAD] = (float(*)[PAD])(sm + 64 * PAD);      // [r][k]
  float (*Vs)[PAD] = (float(*)[PAD])(sm + 2 * 64 * PAD);  // [k][d]
  float (*Ps)[PAD] = (float(*)[PAD])(sm + 3 * 64 * PAD);  // [q][k]

  const int qt = blockIdx.x, h = blockIdx.y, b = blockIdx.z;
  const int t = threadIdx.x, ty = t >> 4, tx = t & 15;
  const int ty4 = ty * 4, tx4 = tx * 4;
  const int hc = h * 64;
  const int tokbase = b * SS;
  const int q0 = qt * 64;

  // load Q tile transposed: Qs[r][q]
#pragma unroll
  for (int it = 0; it < 4; it++) {
    int f = t + it * 256;
    int tok = f >> 4;
    int rq = (f & 15) << 2;
    float4 qv = *(const float4*)&QL[(tokbase + q0 + tok) * HH + hc + rq];
    Qs[rq+0][tok] = qv.x; Qs[rq+1][tok] = qv.y;
    Qs[rq+2][tok] = qv.z; Qs[rq+3][tok] = qv.w;
  }
  __syncthreads();

  float m_r[4], l_r[4], O[4][4];
#pragma unroll
  for (int i = 0; i < 4; i++) {
    m_r[i] = -1e30f; l_r[i] = 0.f;
#pragma unroll
    for (int j = 0; j < 4; j++) O[i][j] = 0.f;
  }

  for (int kt = 0; kt < SS / 64; kt++) {
    const int k0 = kt * 64;
    // stage K (transposed) and V (natural) via registers
    float4 kreg[4], vreg[4];
#pragma unroll
    for (int it = 0; it < 4; it++) {
      int f = t + it * 256;
      int tok = f >> 4;
      int rq = (f & 15) << 2;
      kreg[it] = *(const float4*)&KL[(tokbase + k0 + tok) * HH + hc + rq];
      vreg[it] = *(const float4*)&V [(tokbase + k0 + tok) * HH + hc + rq];
    }
    __syncthreads();  // previous O-GEMM finished with Ks/Vs/Ps
#pragma unroll
    for (int it = 0; it < 4; it++) {
      int f = t + it * 256;
      int tok = f >> 4;
      int rq = (f & 15) << 2;
      Ks[rq+0][tok] = kreg[it].x; Ks[rq+1][tok] = kreg[it].y;
      Ks[rq+2][tok] = kreg[it].z; Ks[rq+3][tok] = kreg[it].w;
      *(float4*)&Vs[tok][rq] = vreg[it];
    }
    __syncthreads();

    // S = Q @ K^T
    float s[4][4];
#pragma unroll
    for (int i = 0; i < 4; i++)
#pragma unroll
      for (int j = 0; j < 4; j++) s[i][j] = 0.f;
#pragma unroll 8
    for (int r = 0; r < 64; r++) {
      float4 aq = *(const float4*)&Qs[r][ty4];
      float4 bk = *(const float4*)&Ks[r][tx4];
      float a_[4] = {aq.x, aq.y, aq.z, aq.w};
      float b_[4] = {bk.x, bk.y, bk.z, bk.w};
#pragma unroll
      for (int i = 0; i < 4; i++)
#pragma unroll
        for (int j = 0; j < 4; j++) s[i][j] += a_[i] * b_[j];
    }
    // scale + mask
    float4 mk = *(const float4*)&mask[b * SS + k0 + tx4];
    float mka[4] = {mk.x, mk.y, mk.z, mk.w};
#pragma unroll
    for (int i = 0; i < 4; i++)
#pragma unroll
      for (int j = 0; j < 4; j++) s[i][j] = s[i][j] * SCALE + mka[j];

    // online softmax (row stats replicated across 16 lanes of same ty)
#pragma unroll
    for (int i = 0; i < 4; i++) {
      float tm = fmaxf(fmaxf(s[i][0], s[i][1]), fmaxf(s[i][2], s[i][3]));
      tm = fmaxf(tm, __shfl_xor_sync(0xffffffffu, tm, 1));
      tm = fmaxf(tm, __shfl_xor_sync(0xffffffffu, tm, 2));
      tm = fmaxf(tm, __shfl_xor_sync(0xffffffffu, tm, 4));
      tm = fmaxf(tm, __shfl_xor_sync(0xffffffffu, tm, 8));
      float mn = fmaxf(m_r[i], tm);
      float alpha = __expf(m_r[i] - mn);
      m_r[i] = mn;
      float rs = 0.f;
#pragma unroll
      for (int j = 0; j < 4; j++) {
        float p = __expf(s[i][j] - mn);
        s[i][j] = p;
        rs += p;
      }
      rs += __shfl_xor_sync(0xffffffffu, rs, 1);
      rs += __shfl_xor_sync(0xffffffffu, rs, 2);
      rs += __shfl_xor_sync(0xffffffffu, rs, 4);
      rs += __shfl_xor_sync(0xffffffffu, rs, 8);
      l_r[i] = l_r[i] * alpha + rs;
#pragma unroll
      for (int j = 0; j < 4; j++) O[i][j] *= alpha;
      *(float4*)&Ps[ty4 + i][tx4] = make_float4(s[i][0], s[i][1], s[i][2], s[i][3]);
    }
    __syncthreads();

    // O += P @ V
#pragma unroll 8
    for (int k = 0; k < 64; k++) {
      float4 bv = *(const float4*)&Vs[k][tx4];
#pragma unroll
      for (int i = 0; i < 4; i++) {
        float a = Ps[ty4 + i][k];
        O[i][0] += a * bv.x; O[i][1] += a * bv.y;
        O[i][2] += a * bv.z; O[i][3] += a * bv.w;
      }
    }
  }

  // epilogue: normalize and write ctx
#pragma unroll
  for (int i = 0; i < 4; i++) {
    float inv = 1.0f / l_r[i];
    int row = tokbase + q0 + ty4 + i;
    float4 o = make_float4(O[i][0]*inv, O[i][1]*inv, O[i][2]*inv, O[i][3]*inv);
    *(float4*)&CTX[row * HH + hc + tx4] = o;
  }
}

// ---------------- launch ----------------------------------------------------
extern "C" void kernel_launch(void* const* d_in, const int* in_sizes, int n_in,
                              void* d_out, int out_size) {
  const float* x    = (const float*)d_in[0];
  const float* mask = (const float*)d_in[1];
  const float* Wq   = (const float*)d_in[2];
  const float* bq   = (const float*)d_in[3];
  const float* Wk   = (const float*)d_in[4];
  const float* bk   = (const float*)d_in[5];
  const float* Wv   = (const float*)d_in[6];
  const float* bv   = (const float*)d_in[7];
  const float* Wql  = (const float*)d_in[8];
  const float* bql  = (const float*)d_in[9];
  const float* Wkl  = (const float*)d_in[10];
  const float* bkl  = (const float*)d_in[11];
  const float* Wo   = (const float*)d_in[12];
  const float* bo   = (const float*)d_in[13];
  float* out = (float*)d_out;

  float *WqF, *WkF, *bqF, *bkF, *QL, *KL, *Vb, *CTX;
  cudaGetSymbolAddress((void**)&WqF, g_WqF);
  cudaGetSymbolAddress((void**)&WkF, g_WkF);
  cudaGetSymbolAddress((void**)&bqF, g_bqF);
  cudaGetSymbolAddress((void**)&bkF, g_bkF);
  cudaGetSymbolAddress((void**)&QL,  g_QL);
  cudaGetSymbolAddress((void**)&KL,  g_KL);
  cudaGetSymbolAddress((void**)&Vb,  g_V);
  cudaGetSymbolAddress((void**)&CTX, g_CTX);

  cudaFuncSetAttribute(attn_kernel,
                       cudaFuncAttributeMaxDynamicSharedMemorySize, ATTN_SMEM);

  // 1. fold low-rank projections into the token GEMM weights
  fold_w_kernel<<<dim3(NH, 16), 256>>>(Wq, Wql, WqF);
  fold_w_kernel<<<dim3(NH, 16), 256>>>(Wk, Wkl, WkF);
  fold_b_kernel<<<4, 256>>>(bq, Wql, bql, bqF);
  fold_b_kernel<<<4, 256>>>(bk, Wkl, bkl, bkF);

  // 2. projections: QL/KL directly in low-rank space, V
  gemm_bias_kernel<<<dim3(8, 32), 256>>>(x, WqF, bqF, QL);
  gemm_bias_kernel<<<dim3(8, 32), 256>>>(x, WkF, bkF, KL);
  gemm_bias_kernel<<<dim3(8, 32), 256>>>(x, Wv, bv, Vb);

  // 3. fused attention
  attn_kernel<<<dim3(SS/64, NH, BB), 256, ATTN_SMEM>>>(QL, KL, Vb, mask, CTX);

  // 4. output projection
  gemm_bias_kernel<<<dim3(8, 32), 256>>>(CTX, Wo, bo, out);
}

// round 3
// speedup vs baseline: 2.4486x; 2.4486x over previous
#include <cuda_runtime.h>
#include <cuda_bf16.h>
#include <cstdint>
#include <math.h>

// Problem constants
#define BB 2
#define SS 2048
#define HH 1024
#define NH 16
#define HD 64
#define MM (BB*SS)   // 4096 tokens
#define SCALE 0.125f
#define LOG2E 1.4426950408889634f

// ---------------- scratch (device globals: allocation-free) ----------------
__device__ float g_WqF[HH*HH];
__device__ float g_WkF[HH*HH];
__device__ float g_bqF[HH];
__device__ float g_bkF[HH];
__device__ __nv_bfloat16 g_xhi[MM*HH];
__device__ __nv_bfloat16 g_xlo[MM*HH];
__device__ __nv_bfloat16 g_QLhi[MM*HH];
__device__ __nv_bfloat16 g_QLlo[MM*HH];
__device__ __nv_bfloat16 g_KLhi[MM*HH];
__device__ __nv_bfloat16 g_KLlo[MM*HH];
__device__ __nv_bfloat16 g_Vhi[MM*HH];
__device__ __nv_bfloat16 g_Vlo[MM*HH];
__device__ __nv_bfloat16 g_Chi[MM*HH];
__device__ __nv_bfloat16 g_Clo[MM*HH];
__device__ __nv_bfloat16 g_Bqhi[HH*HH];
__device__ __nv_bfloat16 g_Bqlo[HH*HH];
__device__ __nv_bfloat16 g_Bkhi[HH*HH];
__device__ __nv_bfloat16 g_Bklo[HH*HH];
__device__ __nv_bfloat16 g_Bvhi[HH*HH];
__device__ __nv_bfloat16 g_Bvlo[HH*HH];
__device__ __nv_bfloat16 g_Bohi[HH*HH];
__device__ __nv_bfloat16 g_Bolo[HH*HH];

// ================= warp-level MMA helpers (sm_80+ PTX, no 'a' features) =====
static __device__ __forceinline__ uint32_t smem_u32(const void* p) {
  uint32_t a;
  asm("{ .reg .u64 t; cvta.to.shared.u64 t, %1; cvt.u32.u64 %0, t; }"
      : "=r"(a) : "l"(p));
  return a;
}
static __device__ __forceinline__ void ldsm4(uint32_t* r, uint32_t a) {
  asm volatile("ldmatrix.sync.aligned.m8n8.x4.shared.b16 {%0,%1,%2,%3}, [%4];"
               : "=r"(r[0]), "=r"(r[1]), "=r"(r[2]), "=r"(r[3]) : "r"(a));
}
static __device__ __forceinline__ void ldsm4t(uint32_t* r, uint32_t a) {
  asm volatile("ldmatrix.sync.aligned.m8n8.x4.trans.shared.b16 {%0,%1,%2,%3}, [%4];"
               : "=r"(r[0]), "=r"(r[1]), "=r"(r[2]), "=r"(r[3]) : "r"(a));
}
static __device__ __forceinline__ void mma16816(float* c, const uint32_t* a,
                                                uint32_t b0, uint32_t b1) {
  asm volatile(
    "mma.sync.aligned.m16n8k16.row.col.f32.bf16.bf16.f32 "
    "{%0,%1,%2,%3}, {%4,%5,%6,%7}, {%8,%9}, {%0,%1,%2,%3};"
    : "+f"(c[0]), "+f"(c[1]), "+f"(c[2]), "+f"(c[3])
    : "r"(a[0]), "r"(a[1]), "r"(a[2]), "r"(a[3]), "r"(b0), "r"(b1));
}
static __device__ __forceinline__ void split2(float x, float y,
                                              uint32_t& h, uint32_t& lo) {
  __nv_bfloat16 bx = __float2bfloat16(x), by = __float2bfloat16(y);
  float rx = x - __bfloat162float(bx), ry = y - __bfloat162float(by);
  __nv_bfloat16 lx = __float2bfloat16(rx), ly = __float2bfloat16(ry);
  __nv_bfloat162 hh; hh.x = bx; hh.y = by;
  __nv_bfloat162 ll; ll.x = lx; ll.y = ly;
  h = *(uint32_t*)&hh; lo = *(uint32_t*)&ll;
}

// ---------------- weight fold: Wf[:, h*64+r] = sum_d W[:, h*64+d]*Wl[d][r] --
__global__ __launch_bounds__(256) void fold_w_kernel(
    const float* __restrict__ W, const float* __restrict__ Wl,
    float* __restrict__ Wf) {
  __shared__ float Ws[64][65];
  __shared__ float Ls[64][65];
  const int h  = blockIdx.x;
  const int i0 = blockIdx.y * 64;
  const int t  = threadIdx.x;
  for (int idx = t; idx < 64*64; idx += 256) {
    int rr = idx >> 6, cc = idx & 63;
    Ws[rr][cc] = W[(i0 + rr) * HH + h * 64 + cc];
    Ls[rr][cc] = Wl[rr * 64 + cc];
  }
  __syncthreads();
  const int ty = t >> 4, tx = t & 15;
  float acc[4][4];
#pragma unroll
  for (int i = 0; i < 4; i++)
#pragma unroll
    for (int j = 0; j < 4; j++) acc[i][j] = 0.f;
#pragma unroll 8
  for (int k = 0; k < 64; k++) {
    float a[4], b[4];
#pragma unroll
    for (int i = 0; i < 4; i++) a[i] = Ws[ty*4+i][k];
#pragma unroll
    for (int j = 0; j < 4; j++) b[j] = Ls[k][tx*4+j];
#pragma unroll
    for (int i = 0; i < 4; i++)
#pragma unroll
      for (int j = 0; j < 4; j++) acc[i][j] += a[i] * b[j];
  }
#pragma unroll
  for (int i = 0; i < 4; i++)
#pragma unroll
    for (int j = 0; j < 4; j++)
      Wf[(i0 + ty*4 + i) * HH + h * 64 + tx*4 + j] = acc[i][j];
}

__global__ void fold_b_kernel(const float* __restrict__ b,
                              const float* __restrict__ Wl,
                              const float* __restrict__ bl,
                              float* __restrict__ bf) {
  int idx = blockIdx.x * 256 + threadIdx.x;
  if (idx < HH) {
    int h = idx >> 6, r = idx & 63;
    float acc = bl[r];
    for (int d = 0; d < 64; d++) acc += b[h * 64 + d] * Wl[d * 64 + r];
    bf[idx] = acc;
  }
}

// ---------------- fp32 -> bf16 hi/lo split -----------------------------------
__global__ __launch_bounds__(256) void split_kernel(
    const float* __restrict__ in, __nv_bfloat16* __restrict__ hi,
    __nv_bfloat16* __restrict__ lo, int n4) {
  int i = blockIdx.x * 256 + threadIdx.x;
  if (i >= n4) return;
  float4 v = ((const float4*)in)[i];
  float a[4] = {v.x, v.y, v.z, v.w};
  unsigned long long uh = 0, ul = 0;
#pragma unroll
  for (int j = 0; j < 4; j++) {
    __nv_bfloat16 h = __float2bfloat16(a[j]);
    __nv_bfloat16 l = __float2bfloat16(a[j] - __bfloat162float(h));
    uh |= (unsigned long long)__bfloat16_as_ushort(h) << (16 * j);
    ul |= (unsigned long long)__bfloat16_as_ushort(l) << (16 * j);
  }
  ((unsigned long long*)hi)[i] = uh;
  ((unsigned long long*)lo)[i] = ul;
}

// ---------------- transpose + split: T[n][k] = split(W[k][n]) ----------------
__global__ __launch_bounds__(256) void tsplit_kernel(
    const float* __restrict__ W, __nv_bfloat16* __restrict__ Thi,
    __nv_bfloat16* __restrict__ Tlo) {
  __shared__ float tile[32][33];
  const int k0 = blockIdx.y << 5, n0 = blockIdx.x << 5;
  const int tx = threadIdx.x & 31, ty = threadIdx.x >> 5;
#pragma unroll
  for (int i = 0; i < 4; i++)
    tile[ty + i*8][tx] = W[(size_t)(k0 + ty + i*8) * HH + n0 + tx];
  __syncthreads();
#pragma unroll
  for (int i = 0; i < 4; i++) {
    int r = ty + i*8;
    float v = tile[tx][r];
    __nv_bfloat16 h = __float2bfloat16(v);
    __nv_bfloat16 l = __float2bfloat16(v - __bfloat162float(h));
    Thi[(size_t)(n0 + r) * HH + k0 + tx] = h;
    Tlo[(size_t)(n0 + r) * HH + k0 + tx] = l;
  }
}

// ---------------- HMMA split-bf16 GEMM ---------------------------------------
// C[4096,1024] = (Ahi+Alo) @ (Bhi+Blo)^T + bias. A row-major [M,K],
// B row-major [N,K] (pre-transposed weights). Block tile 128x64, K-chunk 64.
// 8 warps in 4(m) x 2(n); warp tile 32x32 (2 m16-tiles x 4 n8-tiles).
// SMEM rows padded to 72 bf16 (144B) -> conflict-free ldmatrix & stores.
#define GSMEM 55296
__global__ __launch_bounds__(256, 2) void gemm_hmma(
    const __nv_bfloat16* __restrict__ Ahi, const __nv_bfloat16* __restrict__ Alo,
    const __nv_bfloat16* __restrict__ Bhi, const __nv_bfloat16* __restrict__ Blo,
    const float* __restrict__ bias, float* __restrict__ Cf,
    __nv_bfloat16* __restrict__ Chi, __nv_bfloat16* __restrict__ Clo,
    int mode) {
  extern __shared__ char sm8[];
  const uint32_t smb = smem_u32(sm8);
  const int t = threadIdx.x, wid = t >> 5, l = t & 31;
  const int n0 = blockIdx.x << 6, m0 = blockIdx.y << 7;
  const int wm = wid >> 1, wn = wid & 1;

  float acc[2][4][4];
#pragma unroll
  for (int a = 0; a < 2; a++)
#pragma unroll
    for (int b = 0; b < 4; b++)
#pragma unroll
      for (int c = 0; c < 4; c++) acc[a][b][c] = 0.f;

  const int lr = t >> 3, lc = t & 7;           // loader: 32 rows x 8 chunks
  const int arow_l = l & 15, acol_off = (l >> 4) << 3;
  const int brow_l = (l & 7) + ((l >> 4) << 3), bcol_off = ((l >> 3) & 1) << 3;

  for (int ch = 0; ch < 16; ch++) {
    const int k0 = ch << 6;
    __syncthreads();
#pragma unroll
    for (int i = 0; i < 4; i++) {
      const int row = lr + (i << 5);
      const size_t g = (size_t)(m0 + row) * HH + k0 + lc * 8;
      const uint32_t so = (uint32_t)(row * 72 + lc * 8) * 2;
      *(uint4*)(sm8 + so)          = *(const uint4*)(Ahi + g);
      *(uint4*)(sm8 + 18432 + so)  = *(const uint4*)(Alo + g);
    }
#pragma unroll
    for (int i = 0; i < 2; i++) {
      const int row = lr + (i << 5);
      const size_t g = (size_t)(n0 + row) * HH + k0 + lc * 8;
      const uint32_t so = (uint32_t)(row * 72 + lc * 8) * 2;
      *(uint4*)(sm8 + 36864 + so)  = *(const uint4*)(Bhi + g);
      *(uint4*)(sm8 + 46080 + so)  = *(const uint4*)(Blo + g);
    }
    __syncthreads();
#pragma unroll
    for (int kc = 0; kc < 4; kc++) {
      uint32_t ah[2][4], al[2][4];
#pragma unroll
      for (int mt = 0; mt < 2; mt++) {
        const uint32_t sa =
            smb + (uint32_t)(((wm << 5) + (mt << 4) + arow_l) * 72 +
                             (kc << 4) + acol_off) * 2;
        ldsm4(ah[mt], sa);
        ldsm4(al[mt], sa + 18432);
      }
      uint32_t bh[8], bl[8];
#pragma unroll
      for (int np = 0; np < 2; np++) {
        const uint32_t sb =
            smb + 36864 + (uint32_t)(((wn << 5) + (np << 4) + brow_l) * 72 +
                                     (kc << 4) + bcol_off) * 2;
        ldsm4(bh + np * 4, sb);
        ldsm4(bl + np * 4, sb + 9216);
      }
#pragma unroll
      for (int mt = 0; mt < 2; mt++)
#pragma unroll
        for (int nt = 0; nt < 4; nt++) {
          mma16816(acc[mt][nt], ah[mt], bh[nt*2], bh[nt*2+1]);
          mma16816(acc[mt][nt], ah[mt], bl[nt*2], bl[nt*2+1]);
          mma16816(acc[mt][nt], al[mt], bh[nt*2], bh[nt*2+1]);
        }
    }
  }
  // epilogue
#pragma unroll
  for (int mt = 0; mt < 2; mt++) {
    const int r1 = m0 + (wm << 5) + (mt << 4) + (l >> 2);
    const int r2 = r1 + 8;
#pragma unroll
    for (int nt = 0; nt < 4; nt++) {
      const int col = n0 + (wn << 5) + (nt << 3) + ((l & 3) << 1);
      const float2 bb = *(const float2*)&bias[col];
      const float v0 = acc[mt][nt][0] + bb.x, v1 = acc[mt][nt][1] + bb.y;
      const float v2 = acc[mt][nt][2] + bb.x, v3 = acc[mt][nt][3] + bb.y;
      if (mode == 0) {
        *(float2*)&Cf[(size_t)r1 * HH + col] = make_float2(v0, v1);
        *(float2*)&Cf[(size_t)r2 * HH + col] = make_float2(v2, v3);
      } else {
        uint32_t h0, l0, h1, l1v;
        split2(v0, v1, h0, l0);
        split2(v2, v3, h1, l1v);
        *(uint32_t*)&Chi[(size_t)r1 * HH + col] = h0;
        *(uint32_t*)&Clo[(size_t)r1 * HH + col] = l0;
        *(uint32_t*)&Chi[(size_t)r2 * HH + col] = h1;
        *(uint32_t*)&Clo[(size_t)r2 * HH + col] = l1v;
      }
    }
  }
}

// ---------------- HMMA flash attention ---------------------------------------
// 64 q-rows per block, 4 warps x 16 rows; k-tiles of 64; split-bf16 S and PV.
// SMEM: K hi/lo + V hi/lo tiles ([64][72] bf16 each) + mask (2048 f32 * log2e).
#define ASMEM 45056
__global__ __launch_bounds__(128, 3) void attn_hmma(
    const __nv_bfloat16* __restrict__ Qhi, const __nv_bfloat16* __restrict__ Qlo,
    const __nv_bfloat16* __restrict__ Khi, const __nv_bfloat16* __restrict__ Klo,
    const __nv_bfloat16* __restrict__ Vhi, const __nv_bfloat16* __restrict__ Vlo,
    const float* __restrict__ mask,
    __nv_bfloat16* __restrict__ Ohi, __nv_bfloat16* __restrict__ Olo) {
  extern __shared__ char sm8[];
  const uint32_t smb = smem_u32(sm8);
  float* smask = (float*)(sm8 + 36864);
  const int t = threadIdx.x, wid = t >> 5, l = t & 31;
  const int qt = blockIdx.x, h = blockIdx.y, b = blockIdx.z;
  const int hc = h << 6, tokbase = b * SS, q0 = qt << 6;

  // stage mask * LOG2E (once)
  for (int i = t; i < SS / 4; i += 128) {
    float4 mv = ((const float4*)(mask + b * SS))[i];
    mv.x *= LOG2E; mv.y *= LOG2E; mv.z *= LOG2E; mv.w *= LOG2E;
    ((float4*)smask)[i] = mv;
  }

  // Q fragments resident in registers (per warp: rows wid*16 .. +15)
  const int grow0 = tokbase + q0 + (wid << 4) + (l >> 2);
  uint32_t qh[4][4], ql[4][4];
#pragma unroll
  for (int kc = 0; kc < 4; kc++)
#pragma unroll
    for (int j = 0; j < 4; j++) {
      const int row = grow0 + ((j & 1) << 3);
      const int k = (kc << 4) + ((l & 3) << 1) + ((j >> 1) << 3);
      qh[kc][j] = *(const uint32_t*)(Qhi + (size_t)row * HH + hc + k);
      ql[kc][j] = *(const uint32_t*)(Qlo + (size_t)row * HH + hc + k);
    }

  float o[8][4];
#pragma unroll
  for (int i = 0; i < 8; i++)
#pragma unroll
    for (int j = 0; j < 4; j++) o[i][j] = 0.f;
  float m1 = -1e30f, m2 = -1e30f, lsum1 = 0.f, lsum2 = 0.f;

  const int lr = t >> 3, lc = t & 7;   // loader: 16 rows x 8 chunks, 4 passes
  const int krow = (l & 7) + ((l >> 4) << 3);
  const int kcol_off = ((l >> 3) & 1) << 3;
  const int vrow = (l & 7) + (((l >> 3) & 1) << 3);
  const int vcol = (l >> 4) << 3;
  const float sl = SCALE * LOG2E;

  for (int kt = 0; kt < SS / 64; kt++) {
    const int k0 = kt << 6;
    __syncthreads();
#pragma unroll
    for (int i = 0; i < 4; i++) {
      const int row = lr + (i << 4);
      const size_t g = (size_t)(tokbase + k0 + row) * HH + hc + lc * 8;
      const uint32_t so = (uint32_t)(row * 72 + lc * 8) * 2;
      *(uint4*)(sm8 + so)         = *(const uint4*)(Khi + g);
      *(uint4*)(sm8 +  9216 + so) = *(const uint4*)(Klo + g);
      *(uint4*)(sm8 + 18432 + so) = *(const uint4*)(Vhi + g);
      *(uint4*)(sm8 + 27648 + so) = *(const uint4*)(Vlo + g);
    }
    __syncthreads();

    // ---- S = Q @ K^T (split) ----
    float sc[8][4];
#pragma unroll
    for (int i = 0; i < 8; i++)
#pragma unroll
      for (int j = 0; j < 4; j++) sc[i][j] = 0.f;
#pragma unroll
    for (int kc = 0; kc < 4; kc++) {
      uint32_t kh[16], kl[16];
#pragma unroll
      for (int np = 0; np < 4; np++) {
        const uint32_t sk =
            smb + (uint32_t)(((np << 4) + krow) * 72 + (kc << 4) + kcol_off) * 2;
        ldsm4(kh + np * 4, sk);
        ldsm4(kl + np * 4, sk + 9216);
      }
#pragma unroll
      for (int nt = 0; nt < 8; nt++) {
        mma16816(sc[nt], qh[kc], kh[nt*2], kh[nt*2+1]);
        mma16816(sc[nt], qh[kc], kl[nt*2], kl[nt*2+1]);
        mma16816(sc[nt], ql[kc], kh[nt*2], kh[nt*2+1]);
      }
    }

    // ---- online softmax (log2 domain) ----
    float nm1 = m1, nm2 = m2;
#pragma unroll
    for (int nt = 0; nt < 8; nt++) {
      const float2 mv = *(const float2*)&smask[k0 + (nt << 3) + ((l & 3) << 1)];
      sc[nt][0] = sc[nt][0] * sl + mv.x;
      sc[nt][1] = sc[nt][1] * sl + mv.y;
      sc[nt][2] = sc[nt][2] * sl + mv.x;
      sc[nt][3] = sc[nt][3] * sl + mv.y;
      nm1 = fmaxf(nm1, fmaxf(sc[nt][0], sc[nt][1]));
      nm2 = fmaxf(nm2, fmaxf(sc[nt][2], sc[nt][3]));
    }
    nm1 = fmaxf(nm1, __shfl_xor_sync(0xffffffffu, nm1, 1));
    nm1 = fmaxf(nm1, __shfl_xor_sync(0xffffffffu, nm1, 2));
    nm2 = fmaxf(nm2, __shfl_xor_sync(0xffffffffu, nm2, 1));
    nm2 = fmaxf(nm2, __shfl_xor_sync(0xffffffffu, nm2, 2));
    const float a1 = exp2f(m1 - nm1), a2 = exp2f(m2 - nm2);
    m1 = nm1; m2 = nm2;
    float rs1 = 0.f, rs2 = 0.f;
#pragma unroll
    for (int nt = 0; nt < 8; nt++) {
      sc[nt][0] = exp2f(sc[nt][0] - m1);
      sc[nt][1] = exp2f(sc[nt][1] - m1);
      sc[nt][2] = exp2f(sc[nt][2] - m2);
      sc[nt][3] = exp2f(sc[nt][3] - m2);
      rs1 += sc[nt][0] + sc[nt][1];
      rs2 += sc[nt][2] + sc[nt][3];
      o[nt][0] *= a1; o[nt][1] *= a1; o[nt][2] *= a2; o[nt][3] *= a2;
    }
    lsum1 = lsum1 * a1 + rs1;
    lsum2 = lsum2 * a2 + rs2;

    // ---- O += P @ V (split) ----
#pragma unroll
    for (int kc2 = 0; kc2 < 4; kc2++) {
      uint32_t ph[4], pl[4];
      split2(sc[2*kc2][0],   sc[2*kc2][1],   ph[0], pl[0]);
      split2(sc[2*kc2][2],   sc[2*kc2][3],   ph[1], pl[1]);
      split2(sc[2*kc2+1][0], sc[2*kc2+1][1], ph[2], pl[2]);
      split2(sc[2*kc2+1][2], sc[2*kc2+1][3], ph[3], pl[3]);
#pragma unroll
      for (int dp = 0; dp < 4; dp++) {
        uint32_t vh[4], vl[4];
        const uint32_t sv =
            smb + 18432 +
            (uint32_t)(((kc2 << 4) + vrow) * 72 + (dp << 4) + vcol) * 2;
        ldsm4t(vh, sv);
        ldsm4t(vl, sv + 9216);
        mma16816(o[2*dp],   ph, vh[0], vh[1]);
        mma16816(o[2*dp],   ph, vl[0], vl[1]);
        mma16816(o[2*dp],   pl, vh[0], vh[1]);
        mma16816(o[2*dp+1], ph, vh[2], vh[3]);
        mma16816(o[2*dp+1], ph, vl[2], vl[3]);
        mma16816(o[2*dp+1], pl, vh[2], vh[3]);
      }
    }
  }

  // ---- epilogue: normalize + split-store CTX as bf16 hi/lo ----
  lsum1 += __shfl_xor_sync(0xffffffffu, lsum1, 1);
  lsum1 += __shfl_xor_sync(0xffffffffu, lsum1, 2);
  lsum2 += __shfl_xor_sync(0xffffffffu, lsum2, 1);
  lsum2 += __shfl_xor_sync(0xffffffffu, lsum2, 2);
  const float i1 = 1.f / lsum1, i2 = 1.f / lsum2;
  const int r1 = grow0, r2 = grow0 + 8;
#pragma unroll
  for (int nt = 0; nt < 8; nt++) {
    const int col = hc + (nt << 3) + ((l & 3) << 1);
    uint32_t h0, l0, h1, l1v;
    split2(o[nt][0] * i1, o[nt][1] * i1, h0, l0);
    split2(o[nt][2] * i2, o[nt][3] * i2, h1, l1v);
    *(uint32_t*)&Ohi[(size_t)r1 * HH + col] = h0;
    *(uint32_t*)&Olo[(size_t)r1 * HH + col] = l0;
    *(uint32_t*)&Ohi[(size_t)r2 * HH + col] = h1;
    *(uint32_t*)&Olo[(size_t)r2 * HH + col] = l1v;
  }
}

// ---------------- launch ------------------------------------------------------
extern "C" void kernel_launch(void* const* d_in, const int* in_sizes, int n_in,
                              void* d_out, int out_size) {
  const float* x    = (const float*)d_in[0];
  const float* mask = (const float*)d_in[1];
  const float* Wq   = (const float*)d_in[2];
  const float* bq   = (const float*)d_in[3];
  const float* Wk   = (const float*)d_in[4];
  const float* bk   = (const float*)d_in[5];
  const float* Wv   = (const float*)d_in[6];
  const float* bv   = (const float*)d_in[7];
  const float* Wql  = (const float*)d_in[8];
  const float* bql  = (const float*)d_in[9];
  const float* Wkl  = (const float*)d_in[10];
  const float* bkl  = (const float*)d_in[11];
  const float* Wo   = (const float*)d_in[12];
  const float* bo   = (const float*)d_in[13];
  float* out = (float*)d_out;

  float *WqF, *WkF, *bqF, *bkF;
  cudaGetSymbolAddress((void**)&WqF, g_WqF);
  cudaGetSymbolAddress((void**)&WkF, g_WkF);
  cudaGetSymbolAddress((void**)&bqF, g_bqF);
  cudaGetSymbolAddress((void**)&bkF, g_bkF);
  __nv_bfloat16 *xhi, *xlo, *QLhi, *QLlo, *KLhi, *KLlo, *Vhi, *Vlo, *Chi, *Clo;
  __nv_bfloat16 *Bqhi, *Bqlo, *Bkhi, *Bklo, *Bvhi, *Bvlo, *Bohi, *Bolo;
  cudaGetSymbolAddress((void**)&xhi, g_xhi);
  cudaGetSymbolAddress((void**)&xlo, g_xlo);
  cudaGetSymbolAddress((void**)&QLhi, g_QLhi);
  cudaGetSymbolAddress((void**)&QLlo, g_QLlo);
  cudaGetSymbolAddress((void**)&KLhi, g_KLhi);
  cudaGetSymbolAddress((void**)&KLlo, g_KLlo);
  cudaGetSymbolAddress((void**)&Vhi, g_Vhi);
  cudaGetSymbolAddress((void**)&Vlo, g_Vlo);
  cudaGetSymbolAddress((void**)&Chi, g_Chi);
  cudaGetSymbolAddress((void**)&Clo, g_Clo);
  cudaGetSymbolAddress((void**)&Bqhi, g_Bqhi);
  cudaGetSymbolAddress((void**)&Bqlo, g_Bqlo);
  cudaGetSymbolAddress((void**)&Bkhi, g_Bkhi);
  cudaGetSymbolAddress((void**)&Bklo, g_Bklo);
  cudaGetSymbolAddress((void**)&Bvhi, g_Bvhi);
  cudaGetSymbolAddress((void**)&Bvlo, g_Bvlo);
  cudaGetSymbolAddress((void**)&Bohi, g_Bohi);
  cudaGetSymbolAddress((void**)&Bolo, g_Bolo);

  cudaFuncSetAttribute(gemm_hmma,
                       cudaFuncAttributeMaxDynamicSharedMemorySize, GSMEM);
  cudaFuncSetAttribute(attn_hmma,
                       cudaFuncAttributeMaxDynamicSharedMemorySize, ASMEM);

  // 1. fold low-rank projections into token-GEMM weights
  fold_w_kernel<<<dim3(NH, 16), 256>>>(Wq, Wql, WqF);
  fold_w_kernel<<<dim3(NH, 16), 256>>>(Wk, Wkl, WkF);
  fold_b_kernel<<<4, 256>>>(bq, Wql, bql, bqF);
  fold_b_kernel<<<4, 256>>>(bk, Wkl, bkl, bkF);

  // 2. split/transpose to bf16 hi/lo
  split_kernel<<<(MM*HH/4 + 255)/256, 256>>>(x, xhi, xlo, MM*HH/4);
  tsplit_kernel<<<dim3(32, 32), 256>>>(WqF, Bqhi, Bqlo);
  tsplit_kernel<<<dim3(32, 32), 256>>>(WkF, Bkhi, Bklo);
  tsplit_kernel<<<dim3(32, 32), 256>>>(Wv,  Bvhi, Bvlo);
  tsplit_kernel<<<dim3(32, 32), 256>>>(Wo,  Bohi, Bolo);

  // 3. HMMA projections -> bf16 hi/lo outputs
  gemm_hmma<<<dim3(16, 32), 256, GSMEM>>>(xhi, xlo, Bqhi, Bqlo, bqF,
                                          nullptr, QLhi, QLlo, 1);
  gemm_hmma<<<dim3(16, 32), 256, GSMEM>>>(xhi, xlo, Bkhi, Bklo, bkF,
                                          nullptr, KLhi, KLlo, 1);
  gemm_hmma<<<dim3(16, 32), 256, GSMEM>>>(xhi, xlo, Bvhi, Bvlo, bv,
                                          nullptr, Vhi, Vlo, 1);

  // 4. HMMA flash attention -> CTX bf16 hi/lo
  attn_hmma<<<dim3(SS/64, NH, BB), 128, ASMEM>>>(QLhi, QLlo, KLhi, KLlo,
                                                 Vhi, Vlo, mask, Chi, Clo);

  // 5. output projection (fp32 out)
  gemm_hmma<<<dim3(16, 32), 256, GSMEM>>>(Chi, Clo, Bohi, Bolo, bo,
                                          out, nullptr, nullptr, 0);
}

// round 4
// speedup vs baseline: 2.9489x; 1.2043x over previous
#include <cuda_runtime.h>
#include <cuda_bf16.h>
#include <cuda_fp16.h>
#include <cstdint>
#include <math.h>

// Problem constants
#define BB 2
#define SS 2048
#define HH 1024
#define NH 16
#define HD 64
#define MM (BB*SS)   // 4096 tokens
#define SCALE 0.125f
#define LOG2E 1.4426950408889634f

// ---------------- scratch (device globals: allocation-free) ----------------
__device__ float g_WqF[HH*HH];
__device__ float g_WkF[HH*HH];
__device__ float g_bqF[HH];
__device__ float g_bkF[HH];
__device__ __nv_bfloat16 g_xhi[MM*HH];
__device__ __nv_bfloat16 g_xlo[MM*HH];
__device__ __half g_Qh[MM*HH];
__device__ __half g_Kh[MM*HH];
__device__ __half g_Vh[MM*HH];
__device__ __half g_Vl[MM*HH];
__device__ __nv_bfloat16 g_Chi[MM*HH];
__device__ __nv_bfloat16 g_Clo[MM*HH];
__device__ __nv_bfloat16 g_Bqhi[HH*HH];
__device__ __nv_bfloat16 g_Bqlo[HH*HH];
__device__ __nv_bfloat16 g_Bkhi[HH*HH];
__device__ __nv_bfloat16 g_Bklo[HH*HH];
__device__ __nv_bfloat16 g_Bvhi[HH*HH];
__device__ __nv_bfloat16 g_Bvlo[HH*HH];
__device__ __nv_bfloat16 g_Bohi[HH*HH];
__device__ __nv_bfloat16 g_Bolo[HH*HH];

// ================= warp-level MMA helpers (sm_80+ PTX, no 'a' features) =====
static __device__ __forceinline__ uint32_t smem_u32(const void* p) {
  uint32_t a;
  asm("{ .reg .u64 t; cvta.to.shared.u64 t, %1; cvt.u32.u64 %0, t; }"
      : "=r"(a) : "l"(p));
  return a;
}
static __device__ __forceinline__ void ldsm4(uint32_t* r, uint32_t a) {
  asm volatile("ldmatrix.sync.aligned.m8n8.x4.shared.b16 {%0,%1,%2,%3}, [%4];"
               : "=r"(r[0]), "=r"(r[1]), "=r"(r[2]), "=r"(r[3]) : "r"(a));
}
static __device__ __forceinline__ void ldsm4t(uint32_t* r, uint32_t a) {
  asm volatile("ldmatrix.sync.aligned.m8n8.x4.trans.shared.b16 {%0,%1,%2,%3}, [%4];"
               : "=r"(r[0]), "=r"(r[1]), "=r"(r[2]), "=r"(r[3]) : "r"(a));
}
static __device__ __forceinline__ void mma16816(float* c, const uint32_t* a,
                                                uint32_t b0, uint32_t b1) {
  asm volatile(
    "mma.sync.aligned.m16n8k16.row.col.f32.bf16.bf16.f32 "
    "{%0,%1,%2,%3}, {%4,%5,%6,%7}, {%8,%9}, {%0,%1,%2,%3};"
    : "+f"(c[0]), "+f"(c[1]), "+f"(c[2]), "+f"(c[3])
    : "r"(a[0]), "r"(a[1]), "r"(a[2]), "r"(a[3]), "r"(b0), "r"(b1));
}
static __device__ __forceinline__ void mma16816h(float* c, const uint32_t* a,
                                                 uint32_t b0, uint32_t b1) {
  asm volatile(
    "mma.sync.aligned.m16n8k16.row.col.f32.f16.f16.f32 "
    "{%0,%1,%2,%3}, {%4,%5,%6,%7}, {%8,%9}, {%0,%1,%2,%3};"
    : "+f"(c[0]), "+f"(c[1]), "+f"(c[2]), "+f"(c[3])
    : "r"(a[0]), "r"(a[1]), "r"(a[2]), "r"(a[3]), "r"(b0), "r"(b1));
}
static __device__ __forceinline__ void split2(float x, float y,
                                              uint32_t& h, uint32_t& lo) {
  __nv_bfloat16 bx = __float2bfloat16(x), by = __float2bfloat16(y);
  float rx = x - __bfloat162float(bx), ry = y - __bfloat162float(by);
  __nv_bfloat16 lx = __float2bfloat16(rx), ly = __float2bfloat16(ry);
  __nv_bfloat162 hh; hh.x = bx; hh.y = by;
  __nv_bfloat162 ll; ll.x = lx; ll.y = ly;
  h = *(uint32_t*)&hh; lo = *(uint32_t*)&ll;
}
static __device__ __forceinline__ uint32_t pack_h2(float x, float y) {
  __half2 h = __floats2half2_rn(x, y);
  return *(uint32_t*)&h;
}
static __device__ __forceinline__ void split2h(float x, float y,
                                               uint32_t& h, uint32_t& lo) {
  __half hx = __float2half_rn(x), hy = __float2half_rn(y);
  __half lx = __float2half_rn(x - __half2float(hx));
  __half ly = __float2half_rn(y - __half2float(hy));
  __half2 hh; hh.x = hx; hh.y = hy;
  __half2 ll; ll.x = lx; ll.y = ly;
  h = *(uint32_t*)&hh; lo = *(uint32_t*)&ll;
}

// ---------------- weight fold: Wf[:, h*64+r] = sum_d W[:, h*64+d]*Wl[d][r] --
__global__ __launch_bounds__(256) void fold_w_kernel(
    const float* __restrict__ W, const float* __restrict__ Wl,
    float* __restrict__ Wf) {
  __shared__ float Ws[64][65];
  __shared__ float Ls[64][65];
  const int h  = blockIdx.x;
  const int i0 = blockIdx.y * 64;
  const int t  = threadIdx.x;
  for (int idx = t; idx < 64*64; idx += 256) {
    int rr = idx >> 6, cc = idx & 63;
    Ws[rr][cc] = W[(i0 + rr) * HH + h * 64 + cc];
    Ls[rr][cc] = Wl[rr * 64 + cc];
  }
  __syncthreads();
  const int ty = t >> 4, tx = t & 15;
  float acc[4][4];
#pragma unroll
  for (int i = 0; i < 4; i++)
#pragma unroll
    for (int j = 0; j < 4; j++) acc[i][j] = 0.f;
#pragma unroll 8
  for (int k = 0; k < 64; k++) {
    float a[4], b[4];
#pragma unroll
    for (int i = 0; i < 4; i++) a[i] = Ws[ty*4+i][k];
#pragma unroll
    for (int j = 0; j < 4; j++) b[j] = Ls[k][tx*4+j];
#pragma unroll
    for (int i = 0; i < 4; i++)
#pragma unroll
      for (int j = 0; j < 4; j++) acc[i][j] += a[i] * b[j];
  }
#pragma unroll
  for (int i = 0; i < 4; i++)
#pragma unroll
    for (int j = 0; j < 4; j++)
      Wf[(i0 + ty*4 + i) * HH + h * 64 + tx*4 + j] = acc[i][j];
}

__global__ void fold_b_kernel(const float* __restrict__ b,
                              const float* __restrict__ Wl,
                              const float* __restrict__ bl,
                              float* __restrict__ bf) {
  int idx = blockIdx.x * 256 + threadIdx.x;
  if (idx < HH) {
    int h = idx >> 6, r = idx & 63;
    float acc = bl[r];
    for (int d = 0; d < 64; d++) acc += b[h * 64 + d] * Wl[d * 64 + r];
    bf[idx] = acc;
  }
}

// ---------------- fp32 -> bf16 hi/lo split -----------------------------------
__global__ __launch_bounds__(256) void split_kernel(
    const float* __restrict__ in, __nv_bfloat16* __restrict__ hi,
    __nv_bfloat16* __restrict__ lo, int n4) {
  int i = blockIdx.x * 256 + threadIdx.x;
  if (i >= n4) return;
  float4 v = ((const float4*)in)[i];
  float a[4] = {v.x, v.y, v.z, v.w};
  unsigned long long uh = 0, ul = 0;
#pragma unroll
  for (int j = 0; j < 4; j++) {
    __nv_bfloat16 h = __float2bfloat16(a[j]);
    __nv_bfloat16 l = __float2bfloat16(a[j] - __bfloat162float(h));
    uh |= (unsigned long long)__bfloat16_as_ushort(h) << (16 * j);
    ul |= (unsigned long long)__bfloat16_as_ushort(l) << (16 * j);
  }
  ((unsigned long long*)hi)[i] = uh;
  ((unsigned long long*)lo)[i] = ul;
}

// ---------------- transpose + split: T[n][k] = split(W[k][n]) ----------------
__global__ __launch_bounds__(256) void tsplit_kernel(
    const float* __restrict__ W, __nv_bfloat16* __restrict__ Thi,
    __nv_bfloat16* __restrict__ Tlo) {
  __shared__ float tile[32][33];
  const int k0 = blockIdx.y << 5, n0 = blockIdx.x << 5;
  const int tx = threadIdx.x & 31, ty = threadIdx.x >> 5;
#pragma unroll
  for (int i = 0; i < 4; i++)
    tile[ty + i*8][tx] = W[(size_t)(k0 + ty + i*8) * HH + n0 + tx];
  __syncthreads();
#pragma unroll
  for (int i = 0; i < 4; i++) {
    int r = ty + i*8;
    float v = tile[tx][r];
    __nv_bfloat16 h = __float2bfloat16(v);
    __nv_bfloat16 l = __float2bfloat16(v - __bfloat162float(h));
    Thi[(size_t)(n0 + r) * HH + k0 + tx] = h;
    Tlo[(size_t)(n0 + r) * HH + k0 + tx] = l;
  }
}

// ---------------- HMMA split-bf16 GEMM ---------------------------------------
// C[4096,1024] = (Ahi+Alo) @ (Bhi+Blo)^T + bias. Block tile 128x64, K-chunk 64.
// 8 warps in 4(m) x 2(n); warp tile 32x32. SMEM rows padded to 72 bf16.
// mode 0: fp32 out (Cf); mode 1: bf16 hi/lo (Chi/Clo);
// mode 2: fp16 single (H1); mode 3: fp16 hi/lo (H1/H2).
#define GSMEM 55296
__global__ __launch_bounds__(256, 2) void gemm_hmma(
    const __nv_bfloat16* __restrict__ Ahi, const __nv_bfloat16* __restrict__ Alo,
    const __nv_bfloat16* __restrict__ Bhi, const __nv_bfloat16* __restrict__ Blo,
    const float* __restrict__ bias, float* __restrict__ Cf,
    __nv_bfloat16* __restrict__ Chi, __nv_bfloat16* __restrict__ Clo,
    __half* __restrict__ H1, __half* __restrict__ H2, int mode) {
  extern __shared__ char sm8[];
  const uint32_t smb = smem_u32(sm8);
  const int t = threadIdx.x, wid = t >> 5, l = t & 31;
  const int n0 = blockIdx.x << 6, m0 = blockIdx.y << 7;
  const int wm = wid >> 1, wn = wid & 1;

  float acc[2][4][4];
#pragma unroll
  for (int a = 0; a < 2; a++)
#pragma unroll
    for (int b = 0; b < 4; b++)
#pragma unroll
      for (int c = 0; c < 4; c++) acc[a][b][c] = 0.f;

  const int lr = t >> 3, lc = t & 7;
  const int arow_l = l & 15, acol_off = (l >> 4) << 3;
  const int brow_l = (l & 7) + ((l >> 4) << 3), bcol_off = ((l >> 3) & 1) << 3;

  for (int ch = 0; ch < 16; ch++) {
    const int k0 = ch << 6;
    __syncthreads();
#pragma unroll
    for (int i = 0; i < 4; i++) {
      const int row = lr + (i << 5);
      const size_t g = (size_t)(m0 + row) * HH + k0 + lc * 8;
      const uint32_t so = (uint32_t)(row * 72 + lc * 8) * 2;
      *(uint4*)(sm8 + so)          = *(const uint4*)(Ahi + g);
      *(uint4*)(sm8 + 18432 + so)  = *(const uint4*)(Alo + g);
    }
#pragma unroll
    for (int i = 0; i < 2; i++) {
      const int row = lr + (i << 5);
      const size_t g = (size_t)(n0 + row) * HH + k0 + lc * 8;
      const uint32_t so = (uint32_t)(row * 72 + lc * 8) * 2;
      *(uint4*)(sm8 + 36864 + so)  = *(const uint4*)(Bhi + g);
      *(uint4*)(sm8 + 46080 + so)  = *(const uint4*)(Blo + g);
    }
    __syncthreads();
#pragma unroll
    for (int kc = 0; kc < 4; kc++) {
      uint32_t ah[2][4], al[2][4];
#pragma unroll
      for (int mt = 0; mt < 2; mt++) {
        const uint32_t sa =
            smb + (uint32_t)(((wm << 5) + (mt << 4) + arow_l) * 72 +
                             (kc << 4) + acol_off) * 2;
        ldsm4(ah[mt], sa);
        ldsm4(al[mt], sa + 18432);
      }
      uint32_t bh[8], bl[8];
#pragma unroll
      for (int np = 0; np < 2; np++) {
        const uint32_t sb =
            smb + 36864 + (uint32_t)(((wn << 5) + (np << 4) + brow_l) * 72 +
                                     (kc << 4) + bcol_off) * 2;
        ldsm4(bh + np * 4, sb);
        ldsm4(bl + np * 4, sb + 9216);
      }
#pragma unroll
      for (int mt = 0; mt < 2; mt++)
#pragma unroll
        for (int nt = 0; nt < 4; nt++) {
          mma16816(acc[mt][nt], ah[mt], bh[nt*2], bh[nt*2+1]);
          mma16816(acc[mt][nt], ah[mt], bl[nt*2], bl[nt*2+1]);
          mma16816(acc[mt][nt], al[mt], bh[nt*2], bh[nt*2+1]);
        }
    }
  }
  // epilogue
#pragma unroll
  for (int mt = 0; mt < 2; mt++) {
    const int r1 = m0 + (wm << 5) + (mt << 4) + (l >> 2);
    const int r2 = r1 + 8;
#pragma unroll
    for (int nt = 0; nt < 4; nt++) {
      const int col = n0 + (wn << 5) + (nt << 3) + ((l & 3) << 1);
      const float2 bb = *(const float2*)&bias[col];
      const float v0 = acc[mt][nt][0] + bb.x, v1 = acc[mt][nt][1] + bb.y;
      const float v2 = acc[mt][nt][2] + bb.x, v3 = acc[mt][nt][3] + bb.y;
      if (mode == 0) {
        *(float2*)&Cf[(size_t)r1 * HH + col] = make_float2(v0, v1);
        *(float2*)&Cf[(size_t)r2 * HH + col] = make_float2(v2, v3);
      } else if (mode == 1) {
        uint32_t h0, l0, h1, l1v;
        split2(v0, v1, h0, l0);
        split2(v2, v3, h1, l1v);
        *(uint32_t*)&Chi[(size_t)r1 * HH + col] = h0;
        *(uint32_t*)&Clo[(size_t)r1 * HH + col] = l0;
        *(uint32_t*)&Chi[(size_t)r2 * HH + col] = h1;
        *(uint32_t*)&Clo[(size_t)r2 * HH + col] = l1v;
      } else if (mode == 2) {
        *(uint32_t*)&H1[(size_t)r1 * HH + col] = pack_h2(v0, v1);
        *(uint32_t*)&H1[(size_t)r2 * HH + col] = pack_h2(v2, v3);
      } else {
        uint32_t h0, l0, h1, l1v;
        split2h(v0, v1, h0, l0);
        split2h(v2, v3, h1, l1v);
        *(uint32_t*)&H1[(size_t)r1 * HH + col] = h0;
        *(uint32_t*)&H2[(size_t)r1 * HH + col] = l0;
        *(uint32_t*)&H1[(size_t)r2 * HH + col] = h1;
        *(uint32_t*)&H2[(size_t)r2 * HH + col] = l1v;
      }
    }
  }
}

// ---------------- fp16 HMMA flash attention -----------------------------------
// 64 q-rows per block, 4 warps x 16 rows; k-tiles of 64.
// S = Q@K^T single fp16 MMA; O += P@(Vhi+Vlo), P fp16 single, V fp16 split.
// SMEM: K fp16 tile + Vhi + Vlo ([64][72] each, 9216B) + mask (8192B).
#define ASMEM 35840
__global__ __launch_bounds__(128, 3) void attn_hmma(
    const __half* __restrict__ Qh, const __half* __restrict__ Kh,
    const __half* __restrict__ Vhi, const __half* __restrict__ Vlo,
    const float* __restrict__ mask,
    __nv_bfloat16* __restrict__ Ohi, __nv_bfloat16* __restrict__ Olo) {
  extern __shared__ char sm8[];
  const uint32_t smb = smem_u32(sm8);
  float* smask = (float*)(sm8 + 27648);
  const int t = threadIdx.x, wid = t >> 5, l = t & 31;
  const int qt = blockIdx.x, h = blockIdx.y, b = blockIdx.z;
  const int hc = h << 6, tokbase = b * SS, q0 = qt << 6;

  // stage mask * LOG2E (once)
  for (int i = t; i < SS / 4; i += 128) {
    float4 mv = ((const float4*)(mask + b * SS))[i];
    mv.x *= LOG2E; mv.y *= LOG2E; mv.z *= LOG2E; mv.w *= LOG2E;
    ((float4*)smask)[i] = mv;
  }

  // Q fragments resident in registers (per warp: rows wid*16 .. +15)
  const int grow0 = tokbase + q0 + (wid << 4) + (l >> 2);
  uint32_t qh[4][4];
#pragma unroll
  for (int kc = 0; kc < 4; kc++)
#pragma unroll
    for (int j = 0; j < 4; j++) {
      const int row = grow0 + ((j & 1) << 3);
      const int k = (kc << 4) + ((l & 3) << 1) + ((j >> 1) << 3);
      qh[kc][j] = *(const uint32_t*)(Qh + (size_t)row * HH + hc + k);
    }

  float o[8][4];
#pragma unroll
  for (int i = 0; i < 8; i++)
#pragma unroll
    for (int j = 0; j < 4; j++) o[i][j] = 0.f;
  float m1 = -1e30f, m2 = -1e30f, lsum1 = 0.f, lsum2 = 0.f;

  const int lr = t >> 3, lc = t & 7;
  const int krow = (l & 7) + ((l >> 4) << 3);
  const int kcol_off = ((l >> 3) & 1) << 3;
  const int vrow = (l & 7) + (((l >> 3) & 1) << 3);
  const int vcol = (l >> 4) << 3;
  const float sl = SCALE * LOG2E;

  for (int kt = 0; kt < SS / 64; kt++) {
    const int k0 = kt << 6;
    __syncthreads();
#pragma unroll
    for (int i = 0; i < 4; i++) {
      const int row = lr + (i << 4);
      const size_t g = (size_t)(tokbase + k0 + row) * HH + hc + lc * 8;
      const uint32_t so = (uint32_t)(row * 72 + lc * 8) * 2;
      *(uint4*)(sm8 + so)         = *(const uint4*)(Kh + g);
      *(uint4*)(sm8 +  9216 + so) = *(const uint4*)(Vhi + g);
      *(uint4*)(sm8 + 18432 + so) = *(const uint4*)(Vlo + g);
    }
    __syncthreads();

    // ---- S = Q @ K^T (single fp16) ----
    float sc[8][4];
#pragma unroll
    for (int i = 0; i < 8; i++)
#pragma unroll
      for (int j = 0; j < 4; j++) sc[i][j] = 0.f;
#pragma unroll
    for (int kc = 0; kc < 4; kc++) {
      uint32_t kh[16];
#pragma unroll
      for (int np = 0; np < 4; np++) {
        const uint32_t sk =
            smb + (uint32_t)(((np << 4) + krow) * 72 + (kc << 4) + kcol_off) * 2;
        ldsm4(kh + np * 4, sk);
      }
#pragma unroll
      for (int nt = 0; nt < 8; nt++)
        mma16816h(sc[nt], qh[kc], kh[nt*2], kh[nt*2+1]);
    }

    // ---- online softmax (log2 domain) ----
    float nm1 = m1, nm2 = m2;
#pragma unroll
    for (int nt = 0; nt < 8; nt++) {
      const float2 mv = *(const float2*)&smask[k0 + (nt << 3) + ((l & 3) << 1)];
      sc[nt][0] = sc[nt][0] * sl + mv.x;
      sc[nt][1] = sc[nt][1] * sl + mv.y;
      sc[nt][2] = sc[nt][2] * sl + mv.x;
      sc[nt][3] = sc[nt][3] * sl + mv.y;
      nm1 = fmaxf(nm1, fmaxf(sc[nt][0], sc[nt][1]));
      nm2 = fmaxf(nm2, fmaxf(sc[nt][2], sc[nt][3]));
    }
    nm1 = fmaxf(nm1, __shfl_xor_sync(0xffffffffu, nm1, 1));
    nm1 = fmaxf(nm1, __shfl_xor_sync(0xffffffffu, nm1, 2));
    nm2 = fmaxf(nm2, __shfl_xor_sync(0xffffffffu, nm2, 1));
    nm2 = fmaxf(nm2, __shfl_xor_sync(0xffffffffu, nm2, 2));
    const float a1 = exp2f(m1 - nm1), a2 = exp2f(m2 - nm2);
    m1 = nm1; m2 = nm2;
    float rs1 = 0.f, rs2 = 0.f;
#pragma unroll
    for (int nt = 0; nt < 8; nt++) {
      sc[nt][0] = exp2f(sc[nt][0] - m1);
      sc[nt][1] = exp2f(sc[nt][1] - m1);
      sc[nt][2] = exp2f(sc[nt][2] - m2);
      sc[nt][3] = exp2f(sc[nt][3] - m2);
      rs1 += sc[nt][0] + sc[nt][1];
      rs2 += sc[nt][2] + sc[nt][3];
      o[nt][0] *= a1; o[nt][1] *= a1; o[nt][2] *= a2; o[nt][3] *= a2;
    }
    lsum1 = lsum1 * a1 + rs1;
    lsum2 = lsum2 * a2 + rs2;

    // ---- O += P @ (Vhi + Vlo), P fp16 single ----
#pragma unroll
    for (int kc2 = 0; kc2 < 4; kc2++) {
      uint32_t ph[4];
      ph[0] = pack_h2(sc[2*kc2][0],   sc[2*kc2][1]);
      ph[1] = pack_h2(sc[2*kc2][2],   sc[2*kc2][3]);
      ph[2] = pack_h2(sc[2*kc2+1][0], sc[2*kc2+1][1]);
      ph[3] = pack_h2(sc[2*kc2+1][2], sc[2*kc2+1][3]);
#pragma unroll
      for (int dp = 0; dp < 4; dp++) {
        uint32_t vh[4], vl[4];
        const uint32_t sv =
            smb + 9216 +
            (uint32_t)(((kc2 << 4) + vrow) * 72 + (dp << 4) + vcol) * 2;
        ldsm4t(vh, sv);
        ldsm4t(vl, sv + 9216);
        mma16816h(o[2*dp],   ph, vh[0], vh[1]);
        mma16816h(o[2*dp],   ph, vl[0], vl[1]);
        mma16816h(o[2*dp+1], ph, vh[2], vh[3]);
        mma16816h(o[2*dp+1], ph, vl[2], vl[3]);
      }
    }
  }

  // ---- epilogue: normalize + split-store CTX as bf16 hi/lo ----
  lsum1 += __shfl_xor_sync(0xffffffffu, lsum1, 1);
  lsum1 += __shfl_xor_sync(0xffffffffu, lsum1, 2);
  lsum2 += __shfl_xor_sync(0xffffffffu, lsum2, 1);
  lsum2 += __shfl_xor_sync(0xffffffffu, lsum2, 2);
  const float i1 = 1.f / lsum1, i2 = 1.f / lsum2;
  const int r1 = grow0, r2 = grow0 + 8;
#pragma unroll
  for (int nt = 0; nt < 8; nt++) {
    const int col = hc + (nt << 3) + ((l & 3) << 1);
    uint32_t h0, l0, h1, l1v;
    split2(o[nt][0] * i1, o[nt][1] * i1, h0, l0);
    split2(o[nt][2] * i2, o[nt][3] * i2, h1, l1v);
    *(uint32_t*)&Ohi[(size_t)r1 * HH + col] = h0;
    *(uint32_t*)&Olo[(size_t)r1 * HH + col] = l0;
    *(uint32_t*)&Ohi[(size_t)r2 * HH + col] = h1;
    *(uint32_t*)&Olo[(size_t)r2 * HH + col] = l1v;
  }
}

// ---------------- launch ------------------------------------------------------
extern "C" void kernel_launch(void* const* d_in, const int* in_sizes, int n_in,
                              void* d_out, int out_size) {
  const float* x    = (const float*)d_in[0];
  const float* mask = (const float*)d_in[1];
  const float* Wq   = (const float*)d_in[2];
  const float* bq   = (const float*)d_in[3];
  const float* Wk   = (const float*)d_in[4];
  const float* bk   = (const float*)d_in[5];
  const float* Wv   = (const float*)d_in[6];
  const float* bv   = (const float*)d_in[7];
  const float* Wql  = (const float*)d_in[8];
  const float* bql  = (const float*)d_in[9];
  const float* Wkl  = (const float*)d_in[10];
  const float* bkl  = (const float*)d_in[11];
  const float* Wo   = (const float*)d_in[12];
  const float* bo   = (const float*)d_in[13];
  float* out = (float*)d_out;

  float *WqF, *WkF, *bqF, *bkF;
  cudaGetSymbolAddress((void**)&WqF, g_WqF);
  cudaGetSymbolAddress((void**)&WkF, g_WkF);
  cudaGetSymbolAddress((void**)&bqF, g_bqF);
  cudaGetSymbolAddress((void**)&bkF, g_bkF);
  __nv_bfloat16 *xhi, *xlo, *Chi, *Clo;
  __half *Qhp, *Khp, *Vhp, *Vlp;
  __nv_bfloat16 *Bqhi, *Bqlo, *Bkhi, *Bklo, *Bvhi, *Bvlo, *Bohi, *Bolo;
  cudaGetSymbolAddress((void**)&xhi, g_xhi);
  cudaGetSymbolAddress((void**)&xlo, g_xlo);
  cudaGetSymbolAddress((void**)&Qhp, g_Qh);
  cudaGetSymbolAddress((void**)&Khp, g_Kh);
  cudaGetSymbolAddress((void**)&Vhp, g_Vh);
  cudaGetSymbolAddress((void**)&Vlp, g_Vl);
  cudaGetSymbolAddress((void**)&Chi, g_Chi);
  cudaGetSymbolAddress((void**)&Clo, g_Clo);
  cudaGetSymbolAddress((void**)&Bqhi, g_Bqhi);
  cudaGetSymbolAddress((void**)&Bqlo, g_Bqlo);
  cudaGetSymbolAddress((void**)&Bkhi, g_Bkhi);
  cudaGetSymbolAddress((void**)&Bklo, g_Bklo);
  cudaGetSymbolAddress((void**)&Bvhi, g_Bvhi);
  cudaGetSymbolAddress((void**)&Bvlo, g_Bvlo);
  cudaGetSymbolAddress((void**)&Bohi, g_Bohi);
  cudaGetSymbolAddress((void**)&Bolo, g_Bolo);

  cudaFuncSetAttribute(gemm_hmma,
                       cudaFuncAttributeMaxDynamicSharedMemorySize, GSMEM);
  cudaFuncSetAttribute(attn_hmma,
                       cudaFuncAttributeMaxDynamicSharedMemorySize, ASMEM);

  // 1. fold low-rank projections into token-GEMM weights
  fold_w_kernel<<<dim3(NH, 16), 256>>>(Wq, Wql, WqF);
  fold_w_kernel<<<dim3(NH, 16), 256>>>(Wk, Wkl, WkF);
  fold_b_kernel<<<4, 256>>>(bq, Wql, bql, bqF);
  fold_b_kernel<<<4, 256>>>(bk, Wkl, bkl, bkF);

  // 2. split/transpose to bf16 hi/lo
  split_kernel<<<(MM*HH/4 + 255)/256, 256>>>(x, xhi, xlo, MM*HH/4);
  tsplit_kernel<<<dim3(32, 32), 256>>>(WqF, Bqhi, Bqlo);
  tsplit_kernel<<<dim3(32, 32), 256>>>(WkF, Bkhi, Bklo);
  tsplit_kernel<<<dim3(32, 32), 256>>>(Wv,  Bvhi, Bvlo);
  tsplit_kernel<<<dim3(32, 32), 256>>>(Wo,  Bohi, Bolo);

  // 3. HMMA projections: QL/KL -> fp16, V -> fp16 hi/lo
  gemm_hmma<<<dim3(16, 32), 256, GSMEM>>>(xhi, xlo, Bqhi, Bqlo, bqF,
                                          nullptr, nullptr, nullptr,
                                          Qhp, nullptr, 2);
  gemm_hmma<<<dim3(16, 32), 256, GSMEM>>>(xhi, xlo, Bkhi, Bklo, bkF,
                                          nullptr, nullptr, nullptr,
                                          Khp, nullptr, 2);
  gemm_hmma<<<dim3(16, 32), 256, GSMEM>>>(xhi, xlo, Bvhi, Bvlo, bv,
                                          nullptr, nullptr, nullptr,
                                          Vhp, Vlp, 3);

  // 4. fp16 HMMA flash attention -> CTX bf16 hi/lo
  attn_hmma<<<dim3(SS/64, NH, BB), 128, ASMEM>>>(Qhp, Khp, Vhp, Vlp,
                                                 mask, Chi, Clo);

  // 5. output projection (fp32 out)
  gemm_hmma<<<dim3(16, 32), 256, GSMEM>>>(Chi, Clo, Bohi, Bolo, bo,
                                          out, nullptr, nullptr,
                                          nullptr, nullptr, 0);
}

// round 5
// speedup vs baseline: 3.5240x; 1.1950x over previous
#include <cuda_runtime.h>
#include <cuda_bf16.h>
#include <cuda_fp16.h>
#include <cstdint>
#include <math.h>

// Problem constants
#define BB 2
#define SS 2048
#define HH 1024
#define NH 16
#define HD 64
#define MM (BB*SS)   // 4096 tokens
#define SCALE 0.125f
#define LOG2E 1.4426950408889634f

// ---------------- scratch (device globals: allocation-free) ----------------
__device__ float g_WqF[HH*HH];
__device__ float g_WkF[HH*HH];
__device__ float g_bqF[HH];
__device__ float g_bkF[HH];
__device__ __nv_bfloat16 g_xhi[MM*HH];
__device__ __nv_bfloat16 g_xlo[MM*HH];
__device__ __half g_Qh[MM*HH];
__device__ __half g_Kh[MM*HH];
__device__ __half g_Vh[MM*HH];
__device__ __nv_bfloat16 g_Chi[MM*HH];
__device__ __nv_bfloat16 g_Clo[MM*HH];
__device__ __nv_bfloat16 g_Bqhi[HH*HH];
__device__ __nv_bfloat16 g_Bqlo[HH*HH];
__device__ __nv_bfloat16 g_Bkhi[HH*HH];
__device__ __nv_bfloat16 g_Bklo[HH*HH];
__device__ __nv_bfloat16 g_Bvhi[HH*HH];
__device__ __nv_bfloat16 g_Bvlo[HH*HH];
__device__ __nv_bfloat16 g_Bohi[HH*HH];
__device__ __nv_bfloat16 g_Bolo[HH*HH];

// ================= warp-level MMA helpers (sm_80+ PTX) ======================
static __device__ __forceinline__ uint32_t smem_u32(const void* p) {
  uint32_t a;
  asm("{ .reg .u64 t; cvta.to.shared.u64 t, %1; cvt.u32.u64 %0, t; }"
      : "=r"(a) : "l"(p));
  return a;
}
static __device__ __forceinline__ void ldsm4(uint32_t* r, uint32_t a) {
  asm volatile("ldmatrix.sync.aligned.m8n8.x4.shared.b16 {%0,%1,%2,%3}, [%4];"
               : "=r"(r[0]), "=r"(r[1]), "=r"(r[2]), "=r"(r[3]) : "r"(a));
}
static __device__ __forceinline__ void ldsm4t(uint32_t* r, uint32_t a) {
  asm volatile("ldmatrix.sync.aligned.m8n8.x4.trans.shared.b16 {%0,%1,%2,%3}, [%4];"
               : "=r"(r[0]), "=r"(r[1]), "=r"(r[2]), "=r"(r[3]) : "r"(a));
}
static __device__ __forceinline__ void mma16816(float* c, const uint32_t* a,
                                                uint32_t b0, uint32_t b1) {
  asm volatile(
    "mma.sync.aligned.m16n8k16.row.col.f32.bf16.bf16.f32 "
    "{%0,%1,%2,%3}, {%4,%5,%6,%7}, {%8,%9}, {%0,%1,%2,%3};"
    : "+f"(c[0]), "+f"(c[1]), "+f"(c[2]), "+f"(c[3])
    : "r"(a[0]), "r"(a[1]), "r"(a[2]), "r"(a[3]), "r"(b0), "r"(b1));
}
static __device__ __forceinline__ void mma16816h(float* c, const uint32_t* a,
                                                 uint32_t b0, uint32_t b1) {
  asm volatile(
    "mma.sync.aligned.m16n8k16.row.col.f32.f16.f16.f32 "
    "{%0,%1,%2,%3}, {%4,%5,%6,%7}, {%8,%9}, {%0,%1,%2,%3};"
    : "+f"(c[0]), "+f"(c[1]), "+f"(c[2]), "+f"(c[3])
    : "r"(a[0]), "r"(a[1]), "r"(a[2]), "r"(a[3]), "r"(b0), "r"(b1));
}
static __device__ __forceinline__ void split2(float x, float y,
                                              uint32_t& h, uint32_t& lo) {
  __nv_bfloat16 bx = __float2bfloat16(x), by = __float2bfloat16(y);
  float rx = x - __bfloat162float(bx), ry = y - __bfloat162float(by);
  __nv_bfloat16 lx = __float2bfloat16(rx), ly = __float2bfloat16(ry);
  __nv_bfloat162 hh; hh.x = bx; hh.y = by;
  __nv_bfloat162 ll; ll.x = lx; ll.y = ly;
  h = *(uint32_t*)&hh; lo = *(uint32_t*)&ll;
}
static __device__ __forceinline__ uint32_t pack_h2(float x, float y) {
  __half2 h = __floats2half2_rn(x, y);
  return *(uint32_t*)&h;
}

// ---------------- weight fold ------------------------------------------------
__global__ __launch_bounds__(256) void fold_w_kernel(
    const float* __restrict__ W, const float* __restrict__ Wl,
    float* __restrict__ Wf) {
  __shared__ float Ws[64][65];
  __shared__ float Ls[64][65];
  const int h  = blockIdx.x;
  const int i0 = blockIdx.y * 64;
  const int t  = threadIdx.x;
  for (int idx = t; idx < 64*64; idx += 256) {
    int rr = idx >> 6, cc = idx & 63;
    Ws[rr][cc] = W[(i0 + rr) * HH + h * 64 + cc];
    Ls[rr][cc] = Wl[rr * 64 + cc];
  }
  __syncthreads();
  const int ty = t >> 4, tx = t & 15;
  float acc[4][4];
#pragma unroll
  for (int i = 0; i < 4; i++)
#pragma unroll
    for (int j = 0; j < 4; j++) acc[i][j] = 0.f;
#pragma unroll 8
  for (int k = 0; k < 64; k++) {
    float a[4], b[4];
#pragma unroll
    for (int i = 0; i < 4; i++) a[i] = Ws[ty*4+i][k];
#pragma unroll
    for (int j = 0; j < 4; j++) b[j] = Ls[k][tx*4+j];
#pragma unroll
    for (int i = 0; i < 4; i++)
#pragma unroll
      for (int j = 0; j < 4; j++) acc[i][j] += a[i] * b[j];
  }
#pragma unroll
  for (int i = 0; i < 4; i++)
#pragma unroll
    for (int j = 0; j < 4; j++)
      Wf[(i0 + ty*4 + i) * HH + h * 64 + tx*4 + j] = acc[i][j];
}

__global__ void fold_b_kernel(const float* __restrict__ b,
                              const float* __restrict__ Wl,
                              const float* __restrict__ bl,
                              float* __restrict__ bf) {
  int idx = blockIdx.x * 256 + threadIdx.x;
  if (idx < HH) {
    int h = idx >> 6, r = idx & 63;
    float acc = bl[r];
    for (int d = 0; d < 64; d++) acc += b[h * 64 + d] * Wl[d * 64 + r];
    bf[idx] = acc;
  }
}

// ---------------- fp32 -> bf16 hi/lo split -----------------------------------
__global__ __launch_bounds__(256) void split_kernel(
    const float* __restrict__ in, __nv_bfloat16* __restrict__ hi,
    __nv_bfloat16* __restrict__ lo, int n4) {
  int i = blockIdx.x * 256 + threadIdx.x;
  if (i >= n4) return;
  float4 v = ((const float4*)in)[i];
  float a[4] = {v.x, v.y, v.z, v.w};
  unsigned long long uh = 0, ul = 0;
#pragma unroll
  for (int j = 0; j < 4; j++) {
    __nv_bfloat16 h = __float2bfloat16(a[j]);
    __nv_bfloat16 l = __float2bfloat16(a[j] - __bfloat162float(h));
    uh |= (unsigned long long)__bfloat16_as_ushort(h) << (16 * j);
    ul |= (unsigned long long)__bfloat16_as_ushort(l) << (16 * j);
  }
  ((unsigned long long*)hi)[i] = uh;
  ((unsigned long long*)lo)[i] = ul;
}

// ---------------- transpose + split ------------------------------------------
__global__ __launch_bounds__(256) void tsplit_kernel(
    const float* __restrict__ W, __nv_bfloat16* __restrict__ Thi,
    __nv_bfloat16* __restrict__ Tlo) {
  __shared__ float tile[32][33];
  const int k0 = blockIdx.y << 5, n0 = blockIdx.x << 5;
  const int tx = threadIdx.x & 31, ty = threadIdx.x >> 5;
#pragma unroll
  for (int i = 0; i < 4; i++)
    tile[ty + i*8][tx] = W[(size_t)(k0 + ty + i*8) * HH + n0 + tx];
  __syncthreads();
#pragma unroll
  for (int i = 0; i < 4; i++) {
    int r = ty + i*8;
    float v = tile[tx][r];
    __nv_bfloat16 h = __float2bfloat16(v);
    __nv_bfloat16 l = __float2bfloat16(v - __bfloat162float(h));
    Thi[(size_t)(n0 + r) * HH + k0 + tx] = h;
    Tlo[(size_t)(n0 + r) * HH + k0 + tx] = l;
  }
}

// ============= shared GEMM body (split-bf16 3-MMA, reg-prefetch) =============
// Block tile 128x64, K-chunk 64. 8 warps 4(m)x2(n), warp tile 32x32.
#define GSMEM 55296
struct GemmAcc { float a[2][4][4]; };

static __device__ __forceinline__ void gemm_core(
    const __nv_bfloat16* __restrict__ Ahi, const __nv_bfloat16* __restrict__ Alo,
    const __nv_bfloat16* __restrict__ Bhi, const __nv_bfloat16* __restrict__ Blo,
    char* sm8, uint32_t smb, int m0, int n0, GemmAcc& A) {
  const int t = threadIdx.x, wid = t >> 5, l = t & 31;
  const int wm = wid >> 1, wn = wid & 1;
  const int lr = t >> 3, lc = t & 7;
  const int arow_l = l & 15, acol_off = (l >> 4) << 3;
  const int brow_l = (l & 7) + ((l >> 4) << 3), bcol_off = ((l >> 3) & 1) << 3;

  uint4 pa0[4], pa1[4], pb0[2], pb1[2];
#define GLOAD(K0) do { \
  _Pragma("unroll") \
  for (int i = 0; i < 4; i++) { \
    const size_t g = (size_t)(m0 + lr + (i << 5)) * HH + (K0) + lc * 8; \
    pa0[i] = *(const uint4*)(Ahi + g); \
    pa1[i] = *(const uint4*)(Alo + g); \
  } \
  _Pragma("unroll") \
  for (int i = 0; i < 2; i++) { \
    const size_t g = (size_t)(n0 + lr + (i << 5)) * HH + (K0) + lc * 8; \
    pb0[i] = *(const uint4*)(Bhi + g); \
    pb1[i] = *(const uint4*)(Blo + g); \
  } } while (0)

  GLOAD(0);
  for (int ch = 0; ch < 16; ch++) {
    __syncthreads();
#pragma unroll
    for (int i = 0; i < 4; i++) {
      const uint32_t so = (uint32_t)((lr + (i << 5)) * 72 + lc * 8) * 2;
      *(uint4*)(sm8 + so)         = pa0[i];
      *(uint4*)(sm8 + 18432 + so) = pa1[i];
    }
#pragma unroll
    for (int i = 0; i < 2; i++) {
      const uint32_t so = (uint32_t)((lr + (i << 5)) * 72 + lc * 8) * 2;
      *(uint4*)(sm8 + 36864 + so) = pb0[i];
      *(uint4*)(sm8 + 46080 + so) = pb1[i];
    }
    __syncthreads();
    if (ch < 15) GLOAD((ch + 1) << 6);
#pragma unroll
    for (int kc = 0; kc < 4; kc++) {
      uint32_t ah[2][4], al[2][4];
#pragma unroll
      for (int mt = 0; mt < 2; mt++) {
        const uint32_t sa =
            smb + (uint32_t)(((wm << 5) + (mt << 4) + arow_l) * 72 +
                             (kc << 4) + acol_off) * 2;
        ldsm4(ah[mt], sa);
        ldsm4(al[mt], sa + 18432);
      }
      uint32_t bh[8], bl[8];
#pragma unroll
      for (int np = 0; np < 2; np++) {
        const uint32_t sb =
            smb + 36864 + (uint32_t)(((wn << 5) + (np << 4) + brow_l) * 72 +
                                     (kc << 4) + bcol_off) * 2;
        ldsm4(bh + np * 4, sb);
        ldsm4(bl + np * 4, sb + 9216);
      }
#pragma unroll
      for (int mt = 0; mt < 2; mt++)
#pragma unroll
        for (int nt = 0; nt < 4; nt++) {
          mma16816(A.a[mt][nt], ah[mt], bh[nt*2], bh[nt*2+1]);
          mma16816(A.a[mt][nt], ah[mt], bl[nt*2], bl[nt*2+1]);
          mma16816(A.a[mt][nt], al[mt], bh[nt*2], bh[nt*2+1]);
        }
    }
  }
#undef GLOAD
}

// ---------------- merged QKV projection GEMM (fp16 single out) ----------------
__global__ __launch_bounds__(256, 2) void qkv_hmma(
    const __nv_bfloat16* __restrict__ Ahi, const __nv_bfloat16* __restrict__ Alo,
    const __nv_bfloat16* __restrict__ Bq0, const __nv_bfloat16* __restrict__ Bq1,
    const __nv_bfloat16* __restrict__ Bk0, const __nv_bfloat16* __restrict__ Bk1,
    const __nv_bfloat16* __restrict__ Bv0, const __nv_bfloat16* __restrict__ Bv1,
    const float* __restrict__ biq, const float* __restrict__ bik,
    const float* __restrict__ biv,
    __half* __restrict__ Oq, __half* __restrict__ Ok, __half* __restrict__ Ov) {
  extern __shared__ char sm8[];
  const uint32_t smb = smem_u32(sm8);
  const int z = blockIdx.z;
  const __nv_bfloat16* Bhi = (z == 0) ? Bq0 : (z == 1) ? Bk0 : Bv0;
  const __nv_bfloat16* Blo = (z == 0) ? Bq1 : (z == 1) ? Bk1 : Bv1;
  const float* bias = (z == 0) ? biq : (z == 1) ? bik : biv;
  __half* H = (z == 0) ? Oq : (z == 1) ? Ok : Ov;
  const int n0 = blockIdx.x << 6, m0 = blockIdx.y << 7;
  const int t = threadIdx.x, wid = t >> 5, l = t & 31;
  const int wm = wid >> 1, wn = wid & 1;

  GemmAcc A;
#pragma unroll
  for (int a = 0; a < 2; a++)
#pragma unroll
    for (int b = 0; b < 4; b++)
#pragma unroll
      for (int c = 0; c < 4; c++) A.a[a][b][c] = 0.f;

  gemm_core(Ahi, Alo, Bhi, Blo, sm8, smb, m0, n0, A);

#pragma unroll
  for (int mt = 0; mt < 2; mt++) {
    const int r1 = m0 + (wm << 5) + (mt << 4) + (l >> 2);
    const int r2 = r1 + 8;
#pragma unroll
    for (int nt = 0; nt < 4; nt++) {
      const int col = n0 + (wn << 5) + (nt << 3) + ((l & 3) << 1);
      const float2 bb = *(const float2*)&bias[col];
      *(uint32_t*)&H[(size_t)r1 * HH + col] =
          pack_h2(A.a[mt][nt][0] + bb.x, A.a[mt][nt][1] + bb.y);
      *(uint32_t*)&H[(size_t)r2 * HH + col] =
          pack_h2(A.a[mt][nt][2] + bb.x, A.a[mt][nt][3] + bb.y);
    }
  }
}

// ---------------- output projection GEMM (fp32 out) ---------------------------
__global__ __launch_bounds__(256, 2) void gemmo_hmma(
    const __nv_bfloat16* __restrict__ Ahi, const __nv_bfloat16* __restrict__ Alo,
    const __nv_bfloat16* __restrict__ Bhi, const __nv_bfloat16* __restrict__ Blo,
    const float* __restrict__ bias, float* __restrict__ Cf) {
  extern __shared__ char sm8[];
  const uint32_t smb = smem_u32(sm8);
  const int n0 = blockIdx.x << 6, m0 = blockIdx.y << 7;
  const int t = threadIdx.x, wid = t >> 5, l = t & 31;
  const int wm = wid >> 1, wn = wid & 1;

  GemmAcc A;
#pragma unroll
  for (int a = 0; a < 2; a++)
#pragma unroll
    for (int b = 0; b < 4; b++)
#pragma unroll
      for (int c = 0; c < 4; c++) A.a[a][b][c] = 0.f;

  gemm_core(Ahi, Alo, Bhi, Blo, sm8, smb, m0, n0, A);

#pragma unroll
  for (int mt = 0; mt < 2; mt++) {
    const int r1 = m0 + (wm << 5) + (mt << 4) + (l >> 2);
    const int r2 = r1 + 8;
#pragma unroll
    for (int nt = 0; nt < 4; nt++) {
      const int col = n0 + (wn << 5) + (nt << 3) + ((l & 3) << 1);
      const float2 bb = *(const float2*)&bias[col];
      *(float2*)&Cf[(size_t)r1 * HH + col] =
          make_float2(A.a[mt][nt][0] + bb.x, A.a[mt][nt][1] + bb.y);
      *(float2*)&Cf[(size_t)r2 * HH + col] =
          make_float2(A.a[mt][nt][2] + bb.x, A.a[mt][nt][3] + bb.y);
    }
  }
}

// ---------------- fp16 HMMA flash attention (single-V, reg-prefetch) ----------
// SMEM: K tile (9216) + V tile (9216) + mask (8192) = 26624.
#define ASMEM 26624
__global__ __launch_bounds__(128, 3) void attn_hmma(
    const __half* __restrict__ Qh, const __half* __restrict__ Kh,
    const __half* __restrict__ Vh, const float* __restrict__ mask,
    __nv_bfloat16* __restrict__ Ohi, __nv_bfloat16* __restrict__ Olo) {
  extern __shared__ char sm8[];
  const uint32_t smb = smem_u32(sm8);
  float* smask = (float*)(sm8 + 18432);
  const int t = threadIdx.x, wid = t >> 5, l = t & 31;
  const int qt = blockIdx.x, h = blockIdx.y, b = blockIdx.z;
  const int hc = h << 6, tokbase = b * SS, q0 = qt << 6;

  // stage mask * LOG2E (once)
  for (int i = t; i < SS / 4; i += 128) {
    float4 mv = ((const float4*)(mask + b * SS))[i];
    mv.x *= LOG2E; mv.y *= LOG2E; mv.z *= LOG2E; mv.w *= LOG2E;
    ((float4*)smask)[i] = mv;
  }

  // Q fragments resident in registers
  const int grow0 = tokbase + q0 + (wid << 4) + (l >> 2);
  uint32_t qh[4][4];
#pragma unroll
  for (int kc = 0; kc < 4; kc++)
#pragma unroll
    for (int j = 0; j < 4; j++) {
      const int row = grow0 + ((j & 1) << 3);
      const int k = (kc << 4) + ((l & 3) << 1) + ((j >> 1) << 3);
      qh[kc][j] = *(const uint32_t*)(Qh + (size_t)row * HH + hc + k);
    }

  float o[8][4];
#pragma unroll
  for (int i = 0; i < 8; i++)
#pragma unroll
    for (int j = 0; j < 4; j++) o[i][j] = 0.f;
  float m1 = -1e30f, m2 = -1e30f, lsum1 = 0.f, lsum2 = 0.f;

  const int lr = t >> 3, lc = t & 7;
  const int krow = (l & 7) + ((l >> 4) << 3);
  const int kcol_off = ((l >> 3) & 1) << 3;
  const int vrow = (l & 7) + (((l >> 3) & 1) << 3);
  const int vcol = (l >> 4) << 3;
  const float sl = SCALE * LOG2E;

  uint4 pk[4], pv[4];
#define ALOAD(K0) do { \
  _Pragma("unroll") \
  for (int i = 0; i < 4; i++) { \
    const size_t g = (size_t)(tokbase + (K0) + lr + (i << 4)) * HH + hc + lc * 8; \
    pk[i] = *(const uint4*)(Kh + g); \
    pv[i] = *(const uint4*)(Vh + g); \
  } } while (0)

  ALOAD(0);
  for (int kt = 0; kt < SS / 64; kt++) {
    const int k0 = kt << 6;
    __syncthreads();
#pragma unroll
    for (int i = 0; i < 4; i++) {
      const uint32_t so = (uint32_t)((lr + (i << 4)) * 72 + lc * 8) * 2;
      *(uint4*)(sm8 + so)        = pk[i];
      *(uint4*)(sm8 + 9216 + so) = pv[i];
    }
    __syncthreads();
    if (kt < SS / 64 - 1) ALOAD(k0 + 64);

    // ---- S = Q @ K^T (single fp16) ----
    float sc[8][4];
#pragma unroll
    for (int i = 0; i < 8; i++)
#pragma unroll
      for (int j = 0; j < 4; j++) sc[i][j] = 0.f;
#pragma unroll
    for (int kc = 0; kc < 4; kc++) {
      uint32_t kh[16];
#pragma unroll
      for (int np = 0; np < 4; np++) {
        const uint32_t sk =
            smb + (uint32_t)(((np << 4) + krow) * 72 + (kc << 4) + kcol_off) * 2;
        ldsm4(kh + np * 4, sk);
      }
#pragma unroll
      for (int nt = 0; nt < 8; nt++)
        mma16816h(sc[nt], qh[kc], kh[nt*2], kh[nt*2+1]);
    }

    // ---- online softmax (log2 domain) ----
    float nm1 = m1, nm2 = m2;
#pragma unroll
    for (int nt = 0; nt < 8; nt++) {
      const float2 mv = *(const float2*)&smask[k0 + (nt << 3) + ((l & 3) << 1)];
      sc[nt][0] = sc[nt][0] * sl + mv.x;
      sc[nt][1] = sc[nt][1] * sl + mv.y;
      sc[nt][2] = sc[nt][2] * sl + mv.x;
      sc[nt][3] = sc[nt][3] * sl + mv.y;
      nm1 = fmaxf(nm1, fmaxf(sc[nt][0], sc[nt][1]));
      nm2 = fmaxf(nm2, fmaxf(sc[nt][2], sc[nt][3]));
    }
    nm1 = fmaxf(nm1, __shfl_xor_sync(0xffffffffu, nm1, 1));
    nm1 = fmaxf(nm1, __shfl_xor_sync(0xffffffffu, nm1, 2));
    nm2 = fmaxf(nm2, __shfl_xor_sync(0xffffffffu, nm2, 1));
    nm2 = fmaxf(nm2, __shfl_xor_sync(0xffffffffu, nm2, 2));
    const float a1 = exp2f(m1 - nm1), a2 = exp2f(m2 - nm2);
    m1 = nm1; m2 = nm2;
    float rs1 = 0.f, rs2 = 0.f;
#pragma unroll
    for (int nt = 0; nt < 8; nt++) {
      sc[nt][0] = exp2f(sc[nt][0] - m1);
      sc[nt][1] = exp2f(sc[nt][1] - m1);
      sc[nt][2] = exp2f(sc[nt][2] - m2);
      sc[nt][3] = exp2f(sc[nt][3] - m2);
      rs1 += sc[nt][0] + sc[nt][1];
      rs2 += sc[nt][2] + sc[nt][3];
      o[nt][0] *= a1; o[nt][1] *= a1; o[nt][2] *= a2; o[nt][3] *= a2;
    }
    lsum1 = lsum1 * a1 + rs1;
    lsum2 = lsum2 * a2 + rs2;

    // ---- O += P @ V (both single fp16) ----
#pragma unroll
    for (int kc2 = 0; kc2 < 4; kc2++) {
      uint32_t ph[4];
      ph[0] = pack_h2(sc[2*kc2][0],   sc[2*kc2][1]);
      ph[1] = pack_h2(sc[2*kc2][2],   sc[2*kc2][3]);
      ph[2] = pack_h2(sc[2*kc2+1][0], sc[2*kc2+1][1]);
      ph[3] = pack_h2(sc[2*kc2+1][2], sc[2*kc2+1][3]);
#pragma unroll
      for (int dp = 0; dp < 4; dp++) {
        uint32_t vh[4];
        const uint32_t sv =
            smb + 9216 +
            (uint32_t)(((kc2 << 4) + vrow) * 72 + (dp << 4) + vcol) * 2;
        ldsm4t(vh, sv);
        mma16816h(o[2*dp],   ph, vh[0], vh[1]);
        mma16816h(o[2*dp+1], ph, vh[2], vh[3]);
      }
    }
  }
#undef ALOAD

  // ---- epilogue: normalize + split-store CTX as bf16 hi/lo ----
  lsum1 += __shfl_xor_sync(0xffffffffu, lsum1, 1);
  lsum1 += __shfl_xor_sync(0xffffffffu, lsum1, 2);
  lsum2 += __shfl_xor_sync(0xffffffffu, lsum2, 1);
  lsum2 += __shfl_xor_sync(0xffffffffu, lsum2, 2);
  const float i1 = 1.f / lsum1, i2 = 1.f / lsum2;
  const int r1 = grow0, r2 = grow0 + 8;
#pragma unroll
  for (int nt = 0; nt < 8; nt++) {
    const int col = hc + (nt << 3) + ((l & 3) << 1);
    uint32_t h0, l0, h1, l1v;
    split2(o[nt][0] * i1, o[nt][1] * i1, h0, l0);
    split2(o[nt][2] * i2, o[nt][3] * i2, h1, l1v);
    *(uint32_t*)&Ohi[(size_t)r1 * HH + col] = h0;
    *(uint32_t*)&Olo[(size_t)r1 * HH + col] = l0;
    *(uint32_t*)&Ohi[(size_t)r2 * HH + col] = h1;
    *(uint32_t*)&Olo[(size_t)r2 * HH + col] = l1v;
  }
}

// ---------------- launch ------------------------------------------------------
extern "C" void kernel_launch(void* const* d_in, const int* in_sizes, int n_in,
                              void* d_out, int out_size) {
  const float* x    = (const float*)d_in[0];
  const float* mask = (const float*)d_in[1];
  const float* Wq   = (const float*)d_in[2];
  const float* bq   = (const float*)d_in[3];
  const float* Wk   = (const float*)d_in[4];
  const float* bk   = (const float*)d_in[5];
  const float* Wv   = (const float*)d_in[6];
  const float* bv   = (const float*)d_in[7];
  const float* Wql  = (const float*)d_in[8];
  const float* bql  = (const float*)d_in[9];
  const float* Wkl  = (const float*)d_in[10];
  const float* bkl  = (const float*)d_in[11];
  const float* Wo   = (const float*)d_in[12];
  const float* bo   = (const float*)d_in[13];
  float* out = (float*)d_out;

  float *WqF, *WkF, *bqF, *bkF;
  cudaGetSymbolAddress((void**)&WqF, g_WqF);
  cudaGetSymbolAddress((void**)&WkF, g_WkF);
  cudaGetSymbolAddress((void**)&bqF, g_bqF);
  cudaGetSymbolAddress((void**)&bkF, g_bkF);
  __nv_bfloat16 *xhi, *xlo, *Chi, *Clo;
  __half *Qhp, *Khp, *Vhp;
  __nv_bfloat16 *Bqhi, *Bqlo, *Bkhi, *Bklo, *Bvhi, *Bvlo, *Bohi, *Bolo;
  cudaGetSymbolAddress((void**)&xhi, g_xhi);
  cudaGetSymbolAddress((void**)&xlo, g_xlo);
  cudaGetSymbolAddress((void**)&Qhp, g_Qh);
  cudaGetSymbolAddress((void**)&Khp, g_Kh);
  cudaGetSymbolAddress((void**)&Vhp, g_Vh);
  cudaGetSymbolAddress((void**)&Chi, g_Chi);
  cudaGetSymbolAddress((void**)&Clo, g_Clo);
  cudaGetSymbolAddress((void**)&Bqhi, g_Bqhi);
  cudaGetSymbolAddress((void**)&Bqlo, g_Bqlo);
  cudaGetSymbolAddress((void**)&Bkhi, g_Bkhi);
  cudaGetSymbolAddress((void**)&Bklo, g_Bklo);
  cudaGetSymbolAddress((void**)&Bvhi, g_Bvhi);
  cudaGetSymbolAddress((void**)&Bvlo, g_Bvlo);
  cudaGetSymbolAddress((void**)&Bohi, g_Bohi);
  cudaGetSymbolAddress((void**)&Bolo, g_Bolo);

  cudaFuncSetAttribute(qkv_hmma,
                       cudaFuncAttributeMaxDynamicSharedMemorySize, GSMEM);
  cudaFuncSetAttribute(gemmo_hmma,
                       cudaFuncAttributeMaxDynamicSharedMemorySize, GSMEM);
  cudaFuncSetAttribute(attn_hmma,
                       cudaFuncAttributeMaxDynamicSharedMemorySize, ASMEM);

  // 1. fold low-rank projections into token-GEMM weights
  fold_w_kernel<<<dim3(NH, 16), 256>>>(Wq, Wql, WqF);
  fold_w_kernel<<<dim3(NH, 16), 256>>>(Wk, Wkl, WkF);
  fold_b_kernel<<<4, 256>>>(bq, Wql, bql, bqF);
  fold_b_kernel<<<4, 256>>>(bk, Wkl, bkl, bkF);

  // 2. split/transpose to bf16 hi/lo
  split_kernel<<<(MM*HH/4 + 255)/256, 256>>>(x, xhi, xlo, MM*HH/4);
  tsplit_kernel<<<dim3(32, 32), 256>>>(WqF, Bqhi, Bqlo);
  tsplit_kernel<<<dim3(32, 32), 256>>>(WkF, Bkhi, Bklo);
  tsplit_kernel<<<dim3(32, 32), 256>>>(Wv,  Bvhi, Bvlo);
  tsplit_kernel<<<dim3(32, 32), 256>>>(Wo,  Bohi, Bolo);

  // 3. merged QKV projection (all fp16 single outputs)
  qkv_hmma<<<dim3(16, 32, 3), 256, GSMEM>>>(
      xhi, xlo, Bqhi, Bqlo, Bkhi, Bklo, Bvhi, Bvlo,
      bqF, bkF, bv, Qhp, Khp, Vhp);

  // 4. fp16 flash attention -> CTX bf16 hi/lo
  attn_hmma<<<dim3(SS/64, NH, BB), 128, ASMEM>>>(Qhp, Khp, Vhp,
                                                 mask, Chi, Clo);

  // 5. output projection (fp32 out)
  gemmo_hmma<<<dim3(16, 32), 256, GSMEM>>>(Chi, Clo, Bohi, Bolo, bo, out);
}

// round 6
// speedup vs baseline: 4.1879x; 1.1884x over previous
#include <cuda_runtime.h>
#include <cuda_bf16.h>
#include <cuda_fp16.h>
#include <cstdint>
#include <math.h>

// Problem constants
#define BB 2
#define SS 2048
#define HH 1024
#define NH 16
#define HD 64
#define MM (BB*SS)   // 4096 tokens
#define SCALE 0.125f
#define LOG2E 1.4426950408889634f

// ---------------- scratch (device globals: allocation-free) ----------------
__device__ float g_WqF[HH*HH];
__device__ float g_WkF[HH*HH];
__device__ float g_bqF[HH];
__device__ float g_bkF[HH];
__device__ __half g_xhi[MM*HH];
__device__ __half g_xlo[MM*HH];
__device__ __half g_Qh[MM*HH];
__device__ __half g_Kh[MM*HH];
__device__ __half g_Vh[MM*HH];
__device__ __half g_Chi[MM*HH];
__device__ __half g_Clo[MM*HH];
__device__ __half g_Bq[HH*HH];
__device__ __half g_Bk[HH*HH];
__device__ __half g_Bv[HH*HH];
__device__ __half g_Bo[HH*HH];

// ================= warp-level MMA helpers (sm_80+ PTX) ======================
static __device__ __forceinline__ uint32_t smem_u32(const void* p) {
  uint32_t a;
  asm("{ .reg .u64 t; cvta.to.shared.u64 t, %1; cvt.u32.u64 %0, t; }"
      : "=r"(a) : "l"(p));
  return a;
}
static __device__ __forceinline__ void ldsm4(uint32_t* r, uint32_t a) {
  asm volatile("ldmatrix.sync.aligned.m8n8.x4.shared.b16 {%0,%1,%2,%3}, [%4];"
               : "=r"(r[0]), "=r"(r[1]), "=r"(r[2]), "=r"(r[3]) : "r"(a));
}
static __device__ __forceinline__ void ldsm4t(uint32_t* r, uint32_t a) {
  asm volatile("ldmatrix.sync.aligned.m8n8.x4.trans.shared.b16 {%0,%1,%2,%3}, [%4];"
               : "=r"(r[0]), "=r"(r[1]), "=r"(r[2]), "=r"(r[3]) : "r"(a));
}
static __device__ __forceinline__ void mma16816h(float* c, const uint32_t* a,
                                                 uint32_t b0, uint32_t b1) {
  asm volatile(
    "mma.sync.aligned.m16n8k16.row.col.f32.f16.f16.f32 "
    "{%0,%1,%2,%3}, {%4,%5,%6,%7}, {%8,%9}, {%0,%1,%2,%3};"
    : "+f"(c[0]), "+f"(c[1]), "+f"(c[2]), "+f"(c[3])
    : "r"(a[0]), "r"(a[1]), "r"(a[2]), "r"(a[3]), "r"(b0), "r"(b1));
}
static __device__ __forceinline__ uint32_t pack_h2(float x, float y) {
  __half2 h = __floats2half2_rn(x, y);
  return *(uint32_t*)&h;
}
static __device__ __forceinline__ void split2h(float x, float y,
                                               uint32_t& h, uint32_t& lo) {
  __half hx = __float2half_rn(x), hy = __float2half_rn(y);
  __half lx = __float2half_rn(x - __half2float(hx));
  __half ly = __float2half_rn(y - __half2float(hy));
  __half2 hh; hh.x = hx; hh.y = hy;
  __half2 ll; ll.x = lx; ll.y = ly;
  h = *(uint32_t*)&hh; lo = *(uint32_t*)&ll;
}

// ---------------- weight fold ------------------------------------------------
__global__ __launch_bounds__(256) void fold_w_kernel(
    const float* __restrict__ W, const float* __restrict__ Wl,
    float* __restrict__ Wf) {
  __shared__ float Ws[64][65];
  __shared__ float Ls[64][65];
  const int h  = blockIdx.x;
  const int i0 = blockIdx.y * 64;
  const int t  = threadIdx.x;
  for (int idx = t; idx < 64*64; idx += 256) {
    int rr = idx >> 6, cc = idx & 63;
    Ws[rr][cc] = W[(i0 + rr) * HH + h * 64 + cc];
    Ls[rr][cc] = Wl[rr * 64 + cc];
  }
  __syncthreads();
  const int ty = t >> 4, tx = t & 15;
  float acc[4][4];
#pragma unroll
  for (int i = 0; i < 4; i++)
#pragma unroll
    for (int j = 0; j < 4; j++) acc[i][j] = 0.f;
#pragma unroll 8
  for (int k = 0; k < 64; k++) {
    float a[4], b[4];
#pragma unroll
    for (int i = 0; i < 4; i++) a[i] = Ws[ty*4+i][k];
#pragma unroll
    for (int j = 0; j < 4; j++) b[j] = Ls[k][tx*4+j];
#pragma unroll
    for (int i = 0; i < 4; i++)
#pragma unroll
      for (int j = 0; j < 4; j++) acc[i][j] += a[i] * b[j];
  }
#pragma unroll
  for (int i = 0; i < 4; i++)
#pragma unroll
    for (int j = 0; j < 4; j++)
      Wf[(i0 + ty*4 + i) * HH + h * 64 + tx*4 + j] = acc[i][j];
}

__global__ void fold_b_kernel(const float* __restrict__ b,
                              const float* __restrict__ Wl,
                              const float* __restrict__ bl,
                              float* __restrict__ bf) {
  int idx = blockIdx.x * 256 + threadIdx.x;
  if (idx < HH) {
    int h = idx >> 6, r = idx & 63;
    float acc = bl[r];
    for (int d = 0; d < 64; d++) acc += b[h * 64 + d] * Wl[d * 64 + r];
    bf[idx] = acc;
  }
}

// ---------------- fp32 -> fp16 hi/lo split -----------------------------------
__global__ __launch_bounds__(256) void split_kernel(
    const float* __restrict__ in, __half* __restrict__ hi,
    __half* __restrict__ lo, int n4) {
  int i = blockIdx.x * 256 + threadIdx.x;
  if (i >= n4) return;
  float4 v = ((const float4*)in)[i];
  uint32_t h0, l0, h1, l1;
  split2h(v.x, v.y, h0, l0);
  split2h(v.z, v.w, h1, l1);
  uint2 uh = make_uint2(h0, h1), ul = make_uint2(l0, l1);
  ((uint2*)hi)[i] = uh;
  ((uint2*)lo)[i] = ul;
}

// ---------------- transpose to fp16: T[n][k] = (half)W[k][n] -------------------
__global__ __launch_bounds__(256) void tsplit_kernel(
    const float* __restrict__ W, __half* __restrict__ Th) {
  __shared__ float tile[32][33];
  const int k0 = blockIdx.y << 5, n0 = blockIdx.x << 5;
  const int tx = threadIdx.x & 31, ty = threadIdx.x >> 5;
#pragma unroll
  for (int i = 0; i < 4; i++)
    tile[ty + i*8][tx] = W[(size_t)(k0 + ty + i*8) * HH + n0 + tx];
  __syncthreads();
#pragma unroll
  for (int i = 0; i < 4; i++) {
    int r = ty + i*8;
    Th[(size_t)(n0 + r) * HH + k0 + tx] = __float2half_rn(tile[tx][r]);
  }
}

// ============= shared GEMM body (A fp16 hi/lo x B fp16 single, 2 MMAs) =======
// Block tile 128x64, K-chunk 64. 8 warps 4(m)x2(n), warp tile 32x32.
// SMEM: Ahi 18432 + Alo 18432 + B 9216 = 46080.
#define GSMEM 46080
struct GemmAcc { float a[2][4][4]; };

static __device__ __forceinline__ void gemm_core(
    const __half* __restrict__ Ahi, const __half* __restrict__ Alo,
    const __half* __restrict__ B,
    char* sm8, uint32_t smb, int m0, int n0, GemmAcc& A) {
  const int t = threadIdx.x, wid = t >> 5, l = t & 31;
  const int wm = wid >> 1, wn = wid & 1;
  const int lr = t >> 3, lc = t & 7;
  const int arow_l = l & 15, acol_off = (l >> 4) << 3;
  const int brow_l = (l & 7) + ((l >> 4) << 3), bcol_off = ((l >> 3) & 1) << 3;

  uint4 pa0[4], pa1[4], pb0[2];
#define GLOAD(K0) do { \
  _Pragma("unroll") \
  for (int i = 0; i < 4; i++) { \
    const size_t g = (size_t)(m0 + lr + (i << 5)) * HH + (K0) + lc * 8; \
    pa0[i] = *(const uint4*)(Ahi + g); \
    pa1[i] = *(const uint4*)(Alo + g); \
  } \
  _Pragma("unroll") \
  for (int i = 0; i < 2; i++) { \
    const size_t g = (size_t)(n0 + lr + (i << 5)) * HH + (K0) + lc * 8; \
    pb0[i] = *(const uint4*)(B + g); \
  } } while (0)

  GLOAD(0);
  for (int ch = 0; ch < 16; ch++) {
    __syncthreads();
#pragma unroll
    for (int i = 0; i < 4; i++) {
      const uint32_t so = (uint32_t)((lr + (i << 5)) * 72 + lc * 8) * 2;
      *(uint4*)(sm8 + so)         = pa0[i];
      *(uint4*)(sm8 + 18432 + so) = pa1[i];
    }
#pragma unroll
    for (int i = 0; i < 2; i++) {
      const uint32_t so = (uint32_t)((lr + (i << 5)) * 72 + lc * 8) * 2;
      *(uint4*)(sm8 + 36864 + so) = pb0[i];
    }
    __syncthreads();
    if (ch < 15) GLOAD((ch + 1) << 6);
#pragma unroll
    for (int kc = 0; kc < 4; kc++) {
      uint32_t ah[2][4], al[2][4];
#pragma unroll
      for (int mt = 0; mt < 2; mt++) {
        const uint32_t sa =
            smb + (uint32_t)(((wm << 5) + (mt << 4) + arow_l) * 72 +
                             (kc << 4) + acol_off) * 2;
        ldsm4(ah[mt], sa);
        ldsm4(al[mt], sa + 18432);
      }
      uint32_t bh[8];
#pragma unroll
      for (int np = 0; np < 2; np++) {
        const uint32_t sb =
            smb + 36864 + (uint32_t)(((wn << 5) + (np << 4) + brow_l) * 72 +
                                     (kc << 4) + bcol_off) * 2;
        ldsm4(bh + np * 4, sb);
      }
#pragma unroll
      for (int mt = 0; mt < 2; mt++)
#pragma unroll
        for (int nt = 0; nt < 4; nt++) {
          mma16816h(A.a[mt][nt], ah[mt], bh[nt*2], bh[nt*2+1]);
          mma16816h(A.a[mt][nt], al[mt], bh[nt*2], bh[nt*2+1]);
        }
    }
  }
#undef GLOAD
}

// ---------------- merged QKV projection GEMM (fp16 single out) ----------------
__global__ __launch_bounds__(256, 2) void qkv_hmma(
    const __half* __restrict__ Ahi, const __half* __restrict__ Alo,
    const __half* __restrict__ Bq, const __half* __restrict__ Bk,
    const __half* __restrict__ Bv,
    const float* __restrict__ biq, const float* __restrict__ bik,
    const float* __restrict__ biv,
    __half* __restrict__ Oq, __half* __restrict__ Ok, __half* __restrict__ Ov) {
  extern __shared__ char sm8[];
  const uint32_t smb = smem_u32(sm8);
  const int z = blockIdx.z;
  const __half* B = (z == 0) ? Bq : (z == 1) ? Bk : Bv;
  const float* bias = (z == 0) ? biq : (z == 1) ? bik : biv;
  __half* H = (z == 0) ? Oq : (z == 1) ? Ok : Ov;
  const int n0 = blockIdx.x << 6, m0 = blockIdx.y << 7;
  const int t = threadIdx.x, wid = t >> 5, l = t & 31;
  const int wm = wid >> 1, wn = wid & 1;

  GemmAcc A;
#pragma unroll
  for (int a = 0; a < 2; a++)
#pragma unroll
    for (int b = 0; b < 4; b++)
#pragma unroll
      for (int c = 0; c < 4; c++) A.a[a][b][c] = 0.f;

  gemm_core(Ahi, Alo, B, sm8, smb, m0, n0, A);

#pragma unroll
  for (int mt = 0; mt < 2; mt++) {
    const int r1 = m0 + (wm << 5) + (mt << 4) + (l >> 2);
    const int r2 = r1 + 8;
#pragma unroll
    for (int nt = 0; nt < 4; nt++) {
      const int col = n0 + (wn << 5) + (nt << 3) + ((l & 3) << 1);
      const float2 bb = *(const float2*)&bias[col];
      *(uint32_t*)&H[(size_t)r1 * HH + col] =
          pack_h2(A.a[mt][nt][0] + bb.x, A.a[mt][nt][1] + bb.y);
      *(uint32_t*)&H[(size_t)r2 * HH + col] =
          pack_h2(A.a[mt][nt][2] + bb.x, A.a[mt][nt][3] + bb.y);
    }
  }
}

// ---------------- output projection GEMM (fp32 out) ---------------------------
__global__ __launch_bounds__(256, 2) void gemmo_hmma(
    const __half* __restrict__ Ahi, const __half* __restrict__ Alo,
    const __half* __restrict__ B,
    const float* __restrict__ bias, float* __restrict__ Cf) {
  extern __shared__ char sm8[];
  const uint32_t smb = smem_u32(sm8);
  const int n0 = blockIdx.x << 6, m0 = blockIdx.y << 7;
  const int t = threadIdx.x, wid = t >> 5, l = t & 31;
  const int wm = wid >> 1, wn = wid & 1;

  GemmAcc A;
#pragma unroll
  for (int a = 0; a < 2; a++)
#pragma unroll
    for (int b = 0; b < 4; b++)
#pragma unroll
      for (int c = 0; c < 4; c++) A.a[a][b][c] = 0.f;

  gemm_core(Ahi, Alo, B, sm8, smb, m0, n0, A);

#pragma unroll
  for (int mt = 0; mt < 2; mt++) {
    const int r1 = m0 + (wm << 5) + (mt << 4) + (l >> 2);
    const int r2 = r1 + 8;
#pragma unroll
    for (int nt = 0; nt < 4; nt++) {
      const int col = n0 + (wn << 5) + (nt << 3) + ((l & 3) << 1);
      const float2 bb = *(const float2*)&bias[col];
      *(float2*)&Cf[(size_t)r1 * HH + col] =
          make_float2(A.a[mt][nt][0] + bb.x, A.a[mt][nt][1] + bb.y);
      *(float2*)&Cf[(size_t)r2 * HH + col] =
          make_float2(A.a[mt][nt][2] + bb.x, A.a[mt][nt][3] + bb.y);
    }
  }
}

// ---------------- fp16 HMMA flash attention (single-V, reg-prefetch) ----------
// SMEM: K tile (9216) + V tile (9216) + mask (8192) = 26624.
#define ASMEM 26624
__global__ __launch_bounds__(128, 3) void attn_hmma(
    const __half* __restrict__ Qh, const __half* __restrict__ Kh,
    const __half* __restrict__ Vh, const float* __restrict__ mask,
    __half* __restrict__ Ohi, __half* __restrict__ Olo) {
  extern __shared__ char sm8[];
  const uint32_t smb = smem_u32(sm8);
  float* smask = (float*)(sm8 + 18432);
  const int t = threadIdx.x, wid = t >> 5, l = t & 31;
  const int qt = blockIdx.x, h = blockIdx.y, b = blockIdx.z;
  const int hc = h << 6, tokbase = b * SS, q0 = qt << 6;

  // stage mask * LOG2E (once)
  for (int i = t; i < SS / 4; i += 128) {
    float4 mv = ((const float4*)(mask + b * SS))[i];
    mv.x *= LOG2E; mv.y *= LOG2E; mv.z *= LOG2E; mv.w *= LOG2E;
    ((float4*)smask)[i] = mv;
  }

  // Q fragments resident in registers
  const int grow0 = tokbase + q0 + (wid << 4) + (l >> 2);
  uint32_t qh[4][4];
#pragma unroll
  for (int kc = 0; kc < 4; kc++)
#pragma unroll
    for (int j = 0; j < 4; j++) {
      const int row = grow0 + ((j & 1) << 3);
      const int k = (kc << 4) + ((l & 3) << 1) + ((j >> 1) << 3);
      qh[kc][j] = *(const uint32_t*)(Qh + (size_t)row * HH + hc + k);
    }

  float o[8][4];
#pragma unroll
  for (int i = 0; i < 8; i++)
#pragma unroll
    for (int j = 0; j < 4; j++) o[i][j] = 0.f;
  float m1 = -1e30f, m2 = -1e30f, lsum1 = 0.f, lsum2 = 0.f;

  const int lr = t >> 3, lc = t & 7;
  const int krow = (l & 7) + ((l >> 4) << 3);
  const int kcol_off = ((l >> 3) & 1) << 3;
  const int vrow = (l & 7) + (((l >> 3) & 1) << 3);
  const int vcol = (l >> 4) << 3;
  const float sl = SCALE * LOG2E;

  uint4 pk[4], pv[4];
#define ALOAD(K0) do { \
  _Pragma("unroll") \
  for (int i = 0; i < 4; i++) { \
    const size_t g = (size_t)(tokbase + (K0) + lr + (i << 4)) * HH + hc + lc * 8; \
    pk[i] = *(const uint4*)(Kh + g); \
    pv[i] = *(const uint4*)(Vh + g); \
  } } while (0)

  ALOAD(0);
  for (int kt = 0; kt < SS / 64; kt++) {
    const int k0 = kt << 6;
    __syncthreads();
#pragma unroll
    for (int i = 0; i < 4; i++) {
      const uint32_t so = (uint32_t)((lr + (i << 4)) * 72 + lc * 8) * 2;
      *(uint4*)(sm8 + so)        = pk[i];
      *(uint4*)(sm8 + 9216 + so) = pv[i];
    }
    __syncthreads();
    if (kt < SS / 64 - 1) ALOAD(k0 + 64);

    // ---- S = Q @ K^T (single fp16) ----
    float sc[8][4];
#pragma unroll
    for (int i = 0; i < 8; i++)
#pragma unroll
      for (int j = 0; j < 4; j++) sc[i][j] = 0.f;
#pragma unroll
    for (int kc = 0; kc < 4; kc++) {
      uint32_t kh[16];
#pragma unroll
      for (int np = 0; np < 4; np++) {
        const uint32_t sk =
            smb + (uint32_t)(((np << 4) + krow) * 72 + (kc << 4) + kcol_off) * 2;
        ldsm4(kh + np * 4, sk);
      }
#pragma unroll
      for (int nt = 0; nt < 8; nt++)
        mma16816h(sc[nt], qh[kc], kh[nt*2], kh[nt*2+1]);
    }

    // ---- online softmax (log2 domain) ----
    float nm1 = m1, nm2 = m2;
#pragma unroll
    for (int nt = 0; nt < 8; nt++) {
      const float2 mv = *(const float2*)&smask[k0 + (nt << 3) + ((l & 3) << 1)];
      sc[nt][0] = sc[nt][0] * sl + mv.x;
      sc[nt][1] = sc[nt][1] * sl + mv.y;
      sc[nt][2] = sc[nt][2] * sl + mv.x;
      sc[nt][3] = sc[nt][3] * sl + mv.y;
      nm1 = fmaxf(nm1, fmaxf(sc[nt][0], sc[nt][1]));
      nm2 = fmaxf(nm2, fmaxf(sc[nt][2], sc[nt][3]));
    }
    nm1 = fmaxf(nm1, __shfl_xor_sync(0xffffffffu, nm1, 1));
    nm1 = fmaxf(nm1, __shfl_xor_sync(0xffffffffu, nm1, 2));
    nm2 = fmaxf(nm2, __shfl_xor_sync(0xffffffffu, nm2, 1));
    nm2 = fmaxf(nm2, __shfl_xor_sync(0xffffffffu, nm2, 2));
    const float a1 = exp2f(m1 - nm1), a2 = exp2f(m2 - nm2);
    m1 = nm1; m2 = nm2;
    float rs1 = 0.f, rs2 = 0.f;
#pragma unroll
    for (int nt = 0; nt < 8; nt++) {
      sc[nt][0] = exp2f(sc[nt][0] - m1);
      sc[nt][1] = exp2f(sc[nt][1] - m1);
      sc[nt][2] = exp2f(sc[nt][2] - m2);
      sc[nt][3] = exp2f(sc[nt][3] - m2);
      rs1 += sc[nt][0] + sc[nt][1];
      rs2 += sc[nt][2] + sc[nt][3];
      o[nt][0] *= a1; o[nt][1] *= a1; o[nt][2] *= a2; o[nt][3] *= a2;
    }
    lsum1 = lsum1 * a1 + rs1;
    lsum2 = lsum2 * a2 + rs2;

    // ---- O += P @ V (both single fp16) ----
#pragma unroll
    for (int kc2 = 0; kc2 < 4; kc2++) {
      uint32_t ph[4];
      ph[0] = pack_h2(sc[2*kc2][0],   sc[2*kc2][1]);
      ph[1] = pack_h2(sc[2*kc2][2],   sc[2*kc2][3]);
      ph[2] = pack_h2(sc[2*kc2+1][0], sc[2*kc2+1][1]);
      ph[3] = pack_h2(sc[2*kc2+1][2], sc[2*kc2+1][3]);
#pragma unroll
      for (int dp = 0; dp < 4; dp++) {
        uint32_t vh[4];
        const uint32_t sv =
            smb + 9216 +
            (uint32_t)(((kc2 << 4) + vrow) * 72 + (dp << 4) + vcol) * 2;
        ldsm4t(vh, sv);
        mma16816h(o[2*dp],   ph, vh[0], vh[1]);
        mma16816h(o[2*dp+1], ph, vh[2], vh[3]);
      }
    }
  }
#undef ALOAD

  // ---- epilogue: normalize + split-store CTX as fp16 hi/lo ----
  lsum1 += __shfl_xor_sync(0xffffffffu, lsum1, 1);
  lsum1 += __shfl_xor_sync(0xffffffffu, lsum1, 2);
  lsum2 += __shfl_xor_sync(0xffffffffu, lsum2, 1);
  lsum2 += __shfl_xor_sync(0xffffffffu, lsum2, 2);
  const float i1 = 1.f / lsum1, i2 = 1.f / lsum2;
  const int r1 = grow0, r2 = grow0 + 8;
#pragma unroll
  for (int nt = 0; nt < 8; nt++) {
    const int col = hc + (nt << 3) + ((l & 3) << 1);
    uint32_t h0, l0, h1, l1v;
    split2h(o[nt][0] * i1, o[nt][1] * i1, h0, l0);
    split2h(o[nt][2] * i2, o[nt][3] * i2, h1, l1v);
    *(uint32_t*)&Ohi[(size_t)r1 * HH + col] = h0;
    *(uint32_t*)&Olo[(size_t)r1 * HH + col] = l0;
    *(uint32_t*)&Ohi[(size_t)r2 * HH + col] = h1;
    *(uint32_t*)&Olo[(size_t)r2 * HH + col] = l1v;
  }
}

// ---------------- launch ------------------------------------------------------
extern "C" void kernel_launch(void* const* d_in, const int* in_sizes, int n_in,
                              void* d_out, int out_size) {
  const float* x    = (const float*)d_in[0];
  const float* mask = (const float*)d_in[1];
  const float* Wq   = (const float*)d_in[2];
  const float* bq   = (const float*)d_in[3];
  const float* Wk   = (const float*)d_in[4];
  const float* bk   = (const float*)d_in[5];
  const float* Wv   = (const float*)d_in[6];
  const float* bv   = (const float*)d_in[7];
  const float* Wql  = (const float*)d_in[8];
  const float* bql  = (const float*)d_in[9];
  const float* Wkl  = (const float*)d_in[10];
  const float* bkl  = (const float*)d_in[11];
  const float* Wo   = (const float*)d_in[12];
  const float* bo   = (const float*)d_in[13];
  float* out = (float*)d_out;

  float *WqF, *WkF, *bqF, *bkF;
  cudaGetSymbolAddress((void**)&WqF, g_WqF);
  cudaGetSymbolAddress((void**)&WkF, g_WkF);
  cudaGetSymbolAddress((void**)&bqF, g_bqF);
  cudaGetSymbolAddress((void**)&bkF, g_bkF);
  __half *xhi, *xlo, *Qhp, *Khp, *Vhp, *Chi, *Clo, *Bqp, *Bkp, *Bvp, *Bop;
  cudaGetSymbolAddress((void**)&xhi, g_xhi);
  cudaGetSymbolAddress((void**)&xlo, g_xlo);
  cudaGetSymbolAddress((void**)&Qhp, g_Qh);
  cudaGetSymbolAddress((void**)&Khp, g_Kh);
  cudaGetSymbolAddress((void**)&Vhp, g_Vh);
  cudaGetSymbolAddress((void**)&Chi, g_Chi);
  cudaGetSymbolAddress((void**)&Clo, g_Clo);
  cudaGetSymbolAddress((void**)&Bqp, g_Bq);
  cudaGetSymbolAddress((void**)&Bkp, g_Bk);
  cudaGetSymbolAddress((void**)&Bvp, g_Bv);
  cudaGetSymbolAddress((void**)&Bop, g_Bo);

  cudaFuncSetAttribute(qkv_hmma,
                       cudaFuncAttributeMaxDynamicSharedMemorySize, GSMEM);
  cudaFuncSetAttribute(gemmo_hmma,
                       cudaFuncAttributeMaxDynamicSharedMemorySize, GSMEM);
  cudaFuncSetAttribute(attn_hmma,
                       cudaFuncAttributeMaxDynamicSharedMemorySize, ASMEM);

  // 1. fold low-rank projections into token-GEMM weights
  fold_w_kernel<<<dim3(NH, 16), 256>>>(Wq, Wql, WqF);
  fold_w_kernel<<<dim3(NH, 16), 256>>>(Wk, Wkl, WkF);
  fold_b_kernel<<<4, 256>>>(bq, Wql, bql, bqF);
  fold_b_kernel<<<4, 256>>>(bk, Wkl, bkl, bkF);

  // 2. x -> fp16 hi/lo; weights -> transposed fp16 single
  split_kernel<<<(MM*HH/4 + 255)/256, 256>>>(x, xhi, xlo, MM*HH/4);
  tsplit_kernel<<<dim3(32, 32), 256>>>(WqF, Bqp);
  tsplit_kernel<<<dim3(32, 32), 256>>>(WkF, Bkp);
  tsplit_kernel<<<dim3(32, 32), 256>>>(Wv,  Bvp);
  tsplit_kernel<<<dim3(32, 32), 256>>>(Wo,  Bop);

  // 3. merged QKV projection (fp16 outputs, 2-MMA asymmetric split)
  qkv_hmma<<<dim3(16, 32, 3), 256, GSMEM>>>(
      xhi, xlo, Bqp, Bkp, Bvp, bqF, bkF, bv, Qhp, Khp, Vhp);

  // 4. fp16 flash attention -> CTX fp16 hi/lo
  attn_hmma<<<dim3(SS/64, NH, BB), 128, ASMEM>>>(Qhp, Khp, Vhp,
                                                 mask, Chi, Clo);

  // 5. output projection (fp32 out)
  gemmo_hmma<<<dim3(16, 32), 256, GSMEM>>>(Chi, Clo, Bop, bo, out);
}

// round 7
// speedup vs baseline: 5.6084x; 1.3392x over previous
#include <cuda_runtime.h>
#include <cuda_fp16.h>
#include <cstdint>
#include <math.h>

// Problem constants
#define BB 2
#define SS 2048
#define HH 1024
#define NH 16
#define HD 64
#define MM (BB*SS)   // 4096 tokens
#define SCALE 0.125f
#define LOG2E 1.4426950408889634f

// ---------------- scratch (device globals: allocation-free) ----------------
__device__ float g_WqF[HH*HH];
__device__ float g_WkF[HH*HH];
__device__ float g_bqF[HH];
__device__ float g_bkF[HH];
__device__ __half g_xh[MM*HH];
__device__ __half g_Qh[MM*HH];
__device__ __half g_Kh[MM*HH];
__device__ __half g_Vh[MM*HH];
__device__ __half g_Ch[MM*HH];
__device__ __half g_Bq[HH*HH];
__device__ __half g_Bk[HH*HH];
__device__ __half g_Bv[HH*HH];
__device__ __half g_Bo[HH*HH];

// ================= warp-level MMA helpers (sm_80+ PTX) ======================
static __device__ __forceinline__ uint32_t smem_u32(const void* p) {
  uint32_t a;
  asm("{ .reg .u64 t; cvta.to.shared.u64 t, %1; cvt.u32.u64 %0, t; }"
      : "=r"(a) : "l"(p));
  return a;
}
static __device__ __forceinline__ void ldsm4(uint32_t* r, uint32_t a) {
  asm volatile("ldmatrix.sync.aligned.m8n8.x4.shared.b16 {%0,%1,%2,%3}, [%4];"
               : "=r"(r[0]), "=r"(r[1]), "=r"(r[2]), "=r"(r[3]) : "r"(a));
}
static __device__ __forceinline__ void ldsm4t(uint32_t* r, uint32_t a) {
  asm volatile("ldmatrix.sync.aligned.m8n8.x4.trans.shared.b16 {%0,%1,%2,%3}, [%4];"
               : "=r"(r[0]), "=r"(r[1]), "=r"(r[2]), "=r"(r[3]) : "r"(a));
}
static __device__ __forceinline__ void mma16816h(float* c, const uint32_t* a,
                                                 uint32_t b0, uint32_t b1) {
  asm volatile(
    "mma.sync.aligned.m16n8k16.row.col.f32.f16.f16.f32 "
    "{%0,%1,%2,%3}, {%4,%5,%6,%7}, {%8,%9}, {%0,%1,%2,%3};"
    : "+f"(c[0]), "+f"(c[1]), "+f"(c[2]), "+f"(c[3])
    : "r"(a[0]), "r"(a[1]), "r"(a[2]), "r"(a[3]), "r"(b0), "r"(b1));
}
static __device__ __forceinline__ uint32_t pack_h2(float x, float y) {
  __half2 h = __floats2half2_rn(x, y);
  return *(uint32_t*)&h;
}

// ---------------- weight fold (batched q/k via z) -----------------------------
__global__ __launch_bounds__(256) void fold_w_kernel(
    const float* __restrict__ Wq, const float* __restrict__ Wql,
    const float* __restrict__ Wk, const float* __restrict__ Wkl,
    float* __restrict__ WqF, float* __restrict__ WkF) {
  const float* W  = blockIdx.z ? Wk  : Wq;
  const float* Wl = blockIdx.z ? Wkl : Wql;
  float* Wf       = blockIdx.z ? WkF : WqF;
  __shared__ float Ws[64][65];
  __shared__ float Ls[64][65];
  const int h  = blockIdx.x;
  const int i0 = blockIdx.y * 64;
  const int t  = threadIdx.x;
  for (int idx = t; idx < 64*64; idx += 256) {
    int rr = idx >> 6, cc = idx & 63;
    Ws[rr][cc] = W[(i0 + rr) * HH + h * 64 + cc];
    Ls[rr][cc] = Wl[rr * 64 + cc];
  }
  __syncthreads();
  const int ty = t >> 4, tx = t & 15;
  float acc[4][4];
#pragma unroll
  for (int i = 0; i < 4; i++)
#pragma unroll
    for (int j = 0; j < 4; j++) acc[i][j] = 0.f;
#pragma unroll 8
  for (int k = 0; k < 64; k++) {
    float a[4], b[4];
#pragma unroll
    for (int i = 0; i < 4; i++) a[i] = Ws[ty*4+i][k];
#pragma unroll
    for (int j = 0; j < 4; j++) b[j] = Ls[k][tx*4+j];
#pragma unroll
    for (int i = 0; i < 4; i++)
#pragma unroll
      for (int j = 0; j < 4; j++) acc[i][j] += a[i] * b[j];
  }
#pragma unroll
  for (int i = 0; i < 4; i++)
#pragma unroll
    for (int j = 0; j < 4; j++)
      Wf[(i0 + ty*4 + i) * HH + h * 64 + tx*4 + j] = acc[i][j];
}

__global__ void fold_b_kernel(
    const float* __restrict__ bq, const float* __restrict__ Wql,
    const float* __restrict__ bql,
    const float* __restrict__ bk, const float* __restrict__ Wkl,
    const float* __restrict__ bkl,
    float* __restrict__ bqF, float* __restrict__ bkF) {
  const float* b  = blockIdx.z ? bk  : bq;
  const float* Wl = blockIdx.z ? Wkl : Wql;
  const float* bl = blockIdx.z ? bkl : bql;
  float* bf       = blockIdx.z ? bkF : bqF;
  int idx = blockIdx.x * 256 + threadIdx.x;
  if (idx < HH) {
    int h = idx >> 6, r = idx & 63;
    float acc = bl[r];
    for (int d = 0; d < 64; d++) acc += b[h * 64 + d] * Wl[d * 64 + r];
    bf[idx] = acc;
  }
}

// ---------------- fp32 -> fp16 convert ----------------------------------------
__global__ __launch_bounds__(256) void cvt_kernel(
    const float* __restrict__ in, __half* __restrict__ out, int n4) {
  int i = blockIdx.x * 256 + threadIdx.x;
  if (i >= n4) return;
  float4 v = ((const float4*)in)[i];
  uint2 u;
  u.x = pack_h2(v.x, v.y);
  u.y = pack_h2(v.z, v.w);
  ((uint2*)out)[i] = u;
}

// ---------------- transpose to fp16 (batched 4 weights via z) -----------------
__global__ __launch_bounds__(256) void tcvt_kernel(
    const float* __restrict__ W0, const float* __restrict__ W1,
    const float* __restrict__ W2, const float* __restrict__ W3,
    __half* __restrict__ T0, __half* __restrict__ T1,
    __half* __restrict__ T2, __half* __restrict__ T3) {
  const int z = blockIdx.z;
  const float* W = (z == 0) ? W0 : (z == 1) ? W1 : (z == 2) ? W2 : W3;
  __half* Th     = (z == 0) ? T0 : (z == 1) ? T1 : (z == 2) ? T2 : T3;
  __shared__ float tile[32][33];
  const int k0 = blockIdx.y << 5, n0 = blockIdx.x << 5;
  const int tx = threadIdx.x & 31, ty = threadIdx.x >> 5;
#pragma unroll
  for (int i = 0; i < 4; i++)
    tile[ty + i*8][tx] = W[(size_t)(k0 + ty + i*8) * HH + n0 + tx];
  __syncthreads();
#pragma unroll
  for (int i = 0; i < 4; i++) {
    int r = ty + i*8;
    Th[(size_t)(n0 + r) * HH + k0 + tx] = __float2half_rn(tile[tx][r]);
  }
}

// ============= shared GEMM body (A fp16 x B fp16, 1 MMA per frag) ============
// Block tile 128x64, K-chunk 64. 8 warps 4(m)x2(n), warp tile 32x32.
// SMEM: A 18432 + B 9216 = 27648.
#define GSMEM 27648
struct GemmAcc { float a[2][4][4]; };

static __device__ __forceinline__ void gemm_core(
    const __half* __restrict__ A, const __half* __restrict__ B,
    char* sm8, uint32_t smb, int m0, int n0, GemmAcc& C) {
  const int t = threadIdx.x, wid = t >> 5, l = t & 31;
  const int wm = wid >> 1, wn = wid & 1;
  const int lr = t >> 3, lc = t & 7;
  const int arow_l = l & 15, acol_off = (l >> 4) << 3;
  const int brow_l = (l & 7) + ((l >> 4) << 3), bcol_off = ((l >> 3) & 1) << 3;

  uint4 pa0[4], pb0[2];
#define GLOAD(K0) do { \
  _Pragma("unroll") \
  for (int i = 0; i < 4; i++) { \
    const size_t g = (size_t)(m0 + lr + (i << 5)) * HH + (K0) + lc * 8; \
    pa0[i] = *(const uint4*)(A + g); \
  } \
  _Pragma("unroll") \
  for (int i = 0; i < 2; i++) { \
    const size_t g = (size_t)(n0 + lr + (i << 5)) * HH + (K0) + lc * 8; \
    pb0[i] = *(const uint4*)(B + g); \
  } } while (0)

  GLOAD(0);
  for (int ch = 0; ch < 16; ch++) {
    __syncthreads();
#pragma unroll
    for (int i = 0; i < 4; i++) {
      const uint32_t so = (uint32_t)((lr + (i << 5)) * 72 + lc * 8) * 2;
      *(uint4*)(sm8 + so) = pa0[i];
    }
#pragma unroll
    for (int i = 0; i < 2; i++) {
      const uint32_t so = (uint32_t)((lr + (i << 5)) * 72 + lc * 8) * 2;
      *(uint4*)(sm8 + 18432 + so) = pb0[i];
    }
    __syncthreads();
    if (ch < 15) GLOAD((ch + 1) << 6);
#pragma unroll
    for (int kc = 0; kc < 4; kc++) {
      uint32_t ah[2][4];
#pragma unroll
      for (int mt = 0; mt < 2; mt++) {
        const uint32_t sa =
            smb + (uint32_t)(((wm << 5) + (mt << 4) + arow_l) * 72 +
                             (kc << 4) + acol_off) * 2;
        ldsm4(ah[mt], sa);
      }
      uint32_t bh[8];
#pragma unroll
      for (int np = 0; np < 2; np++) {
        const uint32_t sb =
            smb + 18432 + (uint32_t)(((wn << 5) + (np << 4) + brow_l) * 72 +
                                     (kc << 4) + bcol_off) * 2;
        ldsm4(bh + np * 4, sb);
      }
#pragma unroll
      for (int mt = 0; mt < 2; mt++)
#pragma unroll
        for (int nt = 0; nt < 4; nt++)
          mma16816h(C.a[mt][nt], ah[mt], bh[nt*2], bh[nt*2+1]);
    }
  }
#undef GLOAD
}

// ---------------- merged QKV projection GEMM (fp16 out) -----------------------
__global__ __launch_bounds__(256, 2) void qkv_hmma(
    const __half* __restrict__ Ah,
    const __half* __restrict__ Bq, const __half* __restrict__ Bk,
    const __half* __restrict__ Bv,
    const float* __restrict__ biq, const float* __restrict__ bik,
    const float* __restrict__ biv,
    __half* __restrict__ Oq, __half* __restrict__ Ok, __half* __restrict__ Ov) {
  extern __shared__ char sm8[];
  const uint32_t smb = smem_u32(sm8);
  const int z = blockIdx.z;
  const __half* B = (z == 0) ? Bq : (z == 1) ? Bk : Bv;
  const float* bias = (z == 0) ? biq : (z == 1) ? bik : biv;
  __half* H = (z == 0) ? Oq : (z == 1) ? Ok : Ov;
  const int n0 = blockIdx.x << 6, m0 = blockIdx.y << 7;
  const int t = threadIdx.x, wid = t >> 5, l = t & 31;
  const int wm = wid >> 1, wn = wid & 1;

  GemmAcc C;
#pragma unroll
  for (int a = 0; a < 2; a++)
#pragma unroll
    for (int b = 0; b < 4; b++)
#pragma unroll
      for (int c = 0; c < 4; c++) C.a[a][b][c] = 0.f;

  gemm_core(Ah, B, sm8, smb, m0, n0, C);

#pragma unroll
  for (int mt = 0; mt < 2; mt++) {
    const int r1 = m0 + (wm << 5) + (mt << 4) + (l >> 2);
    const int r2 = r1 + 8;
#pragma unroll
    for (int nt = 0; nt < 4; nt++) {
      const int col = n0 + (wn << 5) + (nt << 3) + ((l & 3) << 1);
      const float2 bb = *(const float2*)&bias[col];
      *(uint32_t*)&H[(size_t)r1 * HH + col] =
          pack_h2(C.a[mt][nt][0] + bb.x, C.a[mt][nt][1] + bb.y);
      *(uint32_t*)&H[(size_t)r2 * HH + col] =
          pack_h2(C.a[mt][nt][2] + bb.x, C.a[mt][nt][3] + bb.y);
    }
  }
}

// ---------------- output projection GEMM (fp32 out) ---------------------------
__global__ __launch_bounds__(256, 2) void gemmo_hmma(
    const __half* __restrict__ Ah, const __half* __restrict__ B,
    const float* __restrict__ bias, float* __restrict__ Cf) {
  extern __shared__ char sm8[];
  const uint32_t smb = smem_u32(sm8);
  const int n0 = blockIdx.x << 6, m0 = blockIdx.y << 7;
  const int t = threadIdx.x, wid = t >> 5, l = t & 31;
  const int wm = wid >> 1, wn = wid & 1;

  GemmAcc C;
#pragma unroll
  for (int a = 0; a < 2; a++)
#pragma unroll
    for (int b = 0; b < 4; b++)
#pragma unroll
      for (int c = 0; c < 4; c++) C.a[a][b][c] = 0.f;

  gemm_core(Ah, B, sm8, smb, m0, n0, C);

#pragma unroll
  for (int mt = 0; mt < 2; mt++) {
    const int r1 = m0 + (wm << 5) + (mt << 4) + (l >> 2);
    const int r2 = r1 + 8;
#pragma unroll
    for (int nt = 0; nt < 4; nt++) {
      const int col = n0 + (wn << 5) + (nt << 3) + ((l & 3) << 1);
      const float2 bb = *(const float2*)&bias[col];
      *(float2*)&Cf[(size_t)r1 * HH + col] =
          make_float2(C.a[mt][nt][0] + bb.x, C.a[mt][nt][1] + bb.y);
      *(float2*)&Cf[(size_t)r2 * HH + col] =
          make_float2(C.a[mt][nt][2] + bb.x, C.a[mt][nt][3] + bb.y);
    }
  }
}

// ---------------- fp16 HMMA flash attention (single-V, reg-prefetch) ----------
// SMEM: K tile (9216) + V tile (9216) + mask (8192) = 26624.
#define ASMEM 26624
__global__ __launch_bounds__(128, 3) void attn_hmma(
    const __half* __restrict__ Qh, const __half* __restrict__ Kh,
    const __half* __restrict__ Vh, const float* __restrict__ mask,
    __half* __restrict__ Oh) {
  extern __shared__ char sm8[];
  const uint32_t smb = smem_u32(sm8);
  float* smask = (float*)(sm8 + 18432);
  const int t = threadIdx.x, wid = t >> 5, l = t & 31;
  const int qt = blockIdx.x, h = blockIdx.y, b = blockIdx.z;
  const int hc = h << 6, tokbase = b * SS, q0 = qt << 6;

  // stage mask * LOG2E (once)
  for (int i = t; i < SS / 4; i += 128) {
    float4 mv = ((const float4*)(mask + b * SS))[i];
    mv.x *= LOG2E; mv.y *= LOG2E; mv.z *= LOG2E; mv.w *= LOG2E;
    ((float4*)smask)[i] = mv;
  }

  // Q fragments resident in registers
  const int grow0 = tokbase + q0 + (wid << 4) + (l >> 2);
  uint32_t qh[4][4];
#pragma unroll
  for (int kc = 0; kc < 4; kc++)
#pragma unroll
    for (int j = 0; j < 4; j++) {
      const int row = grow0 + ((j & 1) << 3);
      const int k = (kc << 4) + ((l & 3) << 1) + ((j >> 1) << 3);
      qh[kc][j] = *(const uint32_t*)(Qh + (size_t)row * HH + hc + k);
    }

  float o[8][4];
#pragma unroll
  for (int i = 0; i < 8; i++)
#pragma unroll
    for (int j = 0; j < 4; j++) o[i][j] = 0.f;
  float m1 = -1e30f, m2 = -1e30f, lsum1 = 0.f, lsum2 = 0.f;

  const int lr = t >> 3, lc = t & 7;
  const int krow = (l & 7) + ((l >> 4) << 3);
  const int kcol_off = ((l >> 3) & 1) << 3;
  const int vrow = (l & 7) + (((l >> 3) & 1) << 3);
  const int vcol = (l >> 4) << 3;
  const float sl = SCALE * LOG2E;

  uint4 pk[4], pv[4];
#define ALOAD(K0) do { \
  _Pragma("unroll") \
  for (int i = 0; i < 4; i++) { \
    const size_t g = (size_t)(tokbase + (K0) + lr + (i << 4)) * HH + hc + lc * 8; \
    pk[i] = *(const uint4*)(Kh + g); \
    pv[i] = *(const uint4*)(Vh + g); \
  } } while (0)

  ALOAD(0);
  for (int kt = 0; kt < SS / 64; kt++) {
    const int k0 = kt << 6;
    __syncthreads();
#pragma unroll
    for (int i = 0; i < 4; i++) {
      const uint32_t so = (uint32_t)((lr + (i << 4)) * 72 + lc * 8) * 2;
      *(uint4*)(sm8 + so)        = pk[i];
      *(uint4*)(sm8 + 9216 + so) = pv[i];
    }
    __syncthreads();
    if (kt < SS / 64 - 1) ALOAD(k0 + 64);

    // ---- S = Q @ K^T (single fp16) ----
    float sc[8][4];
#pragma unroll
    for (int i = 0; i < 8; i++)
#pragma unroll
      for (int j = 0; j < 4; j++) sc[i][j] = 0.f;
#pragma unroll
    for (int kc = 0; kc < 4; kc++) {
      uint32_t kh[16];
#pragma unroll
      for (int np = 0; np < 4; np++) {
        const uint32_t sk =
            smb + (uint32_t)(((np << 4) + krow) * 72 + (kc << 4) + kcol_off) * 2;
        ldsm4(kh + np * 4, sk);
      }
#pragma unroll
      for (int nt = 0; nt < 8; nt++)
        mma16816h(sc[nt], qh[kc], kh[nt*2], kh[nt*2+1]);
    }

    // ---- online softmax (log2 domain) ----
    float nm1 = m1, nm2 = m2;
#pragma unroll
    for (int nt = 0; nt < 8; nt++) {
      const float2 mv = *(const float2*)&smask[k0 + (nt << 3) + ((l & 3) << 1)];
      sc[nt][0] = sc[nt][0] * sl + mv.x;
      sc[nt][1] = sc[nt][1] * sl + mv.y;
      sc[nt][2] = sc[nt][2] * sl + mv.x;
      sc[nt][3] = sc[nt][3] * sl + mv.y;
      nm1 = fmaxf(nm1, fmaxf(sc[nt][0], sc[nt][1]));
      nm2 = fmaxf(nm2, fmaxf(sc[nt][2], sc[nt][3]));
    }
    nm1 = fmaxf(nm1, __shfl_xor_sync(0xffffffffu, nm1, 1));
    nm1 = fmaxf(nm1, __shfl_xor_sync(0xffffffffu, nm1, 2));
    nm2 = fmaxf(nm2, __shfl_xor_sync(0xffffffffu, nm2, 1));
    nm2 = fmaxf(nm2, __shfl_xor_sync(0xffffffffu, nm2, 2));
    const float a1 = exp2f(m1 - nm1), a2 = exp2f(m2 - nm2);
    m1 = nm1; m2 = nm2;
    float rs1 = 0.f, rs2 = 0.f;
#pragma unroll
    for (int nt = 0; nt < 8; nt++) {
      sc[nt][0] = exp2f(sc[nt][0] - m1);
      sc[nt][1] = exp2f(sc[nt][1] - m1);
      sc[nt][2] = exp2f(sc[nt][2] - m2);
      sc[nt][3] = exp2f(sc[nt][3] - m2);
      rs1 += sc[nt][0] + sc[nt][1];
      rs2 += sc[nt][2] + sc[nt][3];
      o[nt][0] *= a1; o[nt][1] *= a1; o[nt][2] *= a2; o[nt][3] *= a2;
    }
    lsum1 = lsum1 * a1 + rs1;
    lsum2 = lsum2 * a2 + rs2;

    // ---- O += P @ V (both single fp16) ----
#pragma unroll
    for (int kc2 = 0; kc2 < 4; kc2++) {
      uint32_t ph[4];
      ph[0] = pack_h2(sc[2*kc2][0],   sc[2*kc2][1]);
      ph[1] = pack_h2(sc[2*kc2][2],   sc[2*kc2][3]);
      ph[2] = pack_h2(sc[2*kc2+1][0], sc[2*kc2+1][1]);
      ph[3] = pack_h2(sc[2*kc2+1][2], sc[2*kc2+1][3]);
#pragma unroll
      for (int dp = 0; dp < 4; dp++) {
        uint32_t vh[4];
        const uint32_t sv =
            smb + 9216 +
            (uint32_t)(((kc2 << 4) + vrow) * 72 + (dp << 4) + vcol) * 2;
        ldsm4t(vh, sv);
        mma16816h(o[2*dp],   ph, vh[0], vh[1]);
        mma16816h(o[2*dp+1], ph, vh[2], vh[3]);
      }
    }
  }
#undef ALOAD

  // ---- epilogue: normalize + store CTX fp16 ----
  lsum1 += __shfl_xor_sync(0xffffffffu, lsum1, 1);
  lsum1 += __shfl_xor_sync(0xffffffffu, lsum1, 2);
  lsum2 += __shfl_xor_sync(0xffffffffu, lsum2, 1);
  lsum2 += __shfl_xor_sync(0xffffffffu, lsum2, 2);
  const float i1 = 1.f / lsum1, i2 = 1.f / lsum2;
  const int r1 = grow0, r2 = grow0 + 8;
#pragma unroll
  for (int nt = 0; nt < 8; nt++) {
    const int col = hc + (nt << 3) + ((l & 3) << 1);
    *(uint32_t*)&Oh[(size_t)r1 * HH + col] =
        pack_h2(o[nt][0] * i1, o[nt][1] * i1);
    *(uint32_t*)&Oh[(size_t)r2 * HH + col] =
        pack_h2(o[nt][2] * i2, o[nt][3] * i2);
  }
}

// ---------------- launch ------------------------------------------------------
extern "C" void kernel_launch(void* const* d_in, const int* in_sizes, int n_in,
                              void* d_out, int out_size) {
  const float* x    = (const float*)d_in[0];
  const float* mask = (const float*)d_in[1];
  const float* Wq   = (const float*)d_in[2];
  const float* bq   = (const float*)d_in[3];
  const float* Wk   = (const float*)d_in[4];
  const float* bk   = (const float*)d_in[5];
  const float* Wv   = (const float*)d_in[6];
  const float* bv   = (const float*)d_in[7];
  const float* Wql  = (const float*)d_in[8];
  const float* bql  = (const float*)d_in[9];
  const float* Wkl  = (const float*)d_in[10];
  const float* bkl  = (const float*)d_in[11];
  const float* Wo   = (const float*)d_in[12];
  const float* bo   = (const float*)d_in[13];
  float* out = (float*)d_out;

  float *WqF, *WkF, *bqF, *bkF;
  cudaGetSymbolAddress((void**)&WqF, g_WqF);
  cudaGetSymbolAddress((void**)&WkF, g_WkF);
  cudaGetSymbolAddress((void**)&bqF, g_bqF);
  cudaGetSymbolAddress((void**)&bkF, g_bkF);
  __half *xh, *Qhp, *Khp, *Vhp, *Chp, *Bqp, *Bkp, *Bvp, *Bop;
  cudaGetSymbolAddress((void**)&xh, g_xh);
  cudaGetSymbolAddress((void**)&Qhp, g_Qh);
  cudaGetSymbolAddress((void**)&Khp, g_Kh);
  cudaGetSymbolAddress((void**)&Vhp, g_Vh);
  cudaGetSymbolAddress((void**)&Chp, g_Ch);
  cudaGetSymbolAddress((void**)&Bqp, g_Bq);
  cudaGetSymbolAddress((void**)&Bkp, g_Bk);
  cudaGetSymbolAddress((void**)&Bvp, g_Bv);
  cudaGetSymbolAddress((void**)&Bop, g_Bo);

  cudaFuncSetAttribute(qkv_hmma,
                       cudaFuncAttributeMaxDynamicSharedMemorySize, GSMEM);
  cudaFuncSetAttribute(gemmo_hmma,
                       cudaFuncAttributeMaxDynamicSharedMemorySize, GSMEM);
  cudaFuncSetAttribute(attn_hmma,
                       cudaFuncAttributeMaxDynamicSharedMemorySize, ASMEM);

  // 1. fold low-rank projections into token-GEMM weights (batched q/k)
  fold_w_kernel<<<dim3(NH, 16, 2), 256>>>(Wq, Wql, Wk, Wkl, WqF, WkF);
  fold_b_kernel<<<dim3(4, 1, 2), 256>>>(bq, Wql, bql, bk, Wkl, bkl, bqF, bkF);

  // 2. x -> fp16 single; weights -> transposed fp16 (batched 4)
  cvt_kernel<<<(MM*HH/4 + 255)/256, 256>>>(x, xh, MM*HH/4);
  tcvt_kernel<<<dim3(32, 32, 4), 256>>>(WqF, WkF, Wv, Wo, Bqp, Bkp, Bvp, Bop);

  // 3. merged QKV projection (fp16 single everywhere, 1 MMA per frag)
  qkv_hmma<<<dim3(16, 32, 3), 256, GSMEM>>>(
      xh, Bqp, Bkp, Bvp, bqF, bkF, bv, Qhp, Khp, Vhp);

  // 4. fp16 flash attention -> CTX fp16 single
  attn_hmma<<<dim3(SS/64, NH, BB), 128, ASMEM>>>(Qhp, Khp, Vhp, mask, Chp);

  // 5. output projection (fp32 out)
  gemmo_hmma<<<dim3(16, 32), 256, GSMEM>>>(Chp, Bop, bo, out);
}